// round 4
// baseline (speedup 1.0000x reference)
#include <cuda_runtime.h>

// Problem constants (fixed by reference setup_inputs)
#define NN 8192
#define DD 64
#define NITER 20
#define REG_E 0.05f
#define INVN (1.0f / 8192.0f)

#define RCHUNK 64
#define ROWS_PER_CHUNK (NN / RCHUNK)   // 128
#define FINAL_BLOCKS 2048

// Scratch: __device__ globals (no allocation allowed in kernel_launch)
__device__ float g_C[(size_t)NN * NN];   // 256 MB cost matrix
__device__ float g_K[(size_t)NN * NN];   // 256 MB Gibbs kernel exp(-C*s)
__device__ float g_x2[NN];
__device__ float g_y2[NN];
__device__ float g_u[NN];
__device__ float g_v[NN];
__device__ unsigned g_cmax_bits;
__device__ float g_cpart[RCHUNK][NN];    // 2 MB column partial sums
__device__ float g_partial[FINAL_BLOCKS];

// ---------------------------------------------------------------------------
// init: v = 1 (first u-update uses v_log = 0), reset max accumulator
// ---------------------------------------------------------------------------
__global__ void init_kernel() {
    int j = blockIdx.x * blockDim.x + threadIdx.x;
    if (j < NN) g_v[j] = 1.0f;
    if (j == 0) g_cmax_bits = 0u;
}

// ---------------------------------------------------------------------------
// squared norms of XP rows (y=0) and XQ rows (y=1)
// ---------------------------------------------------------------------------
__global__ void norms_kernel(const float* __restrict__ XP,
                             const float* __restrict__ XQ) {
    int row = blockIdx.x * blockDim.x + threadIdx.x;
    if (row >= NN) return;
    const float* X = blockIdx.y ? XQ : XP;
    float* out = blockIdx.y ? g_y2 : g_x2;
    const float4* p = (const float4*)(X + (size_t)row * DD);
    float s = 0.0f;
#pragma unroll
    for (int i = 0; i < DD / 4; i++) {
        float4 a = p[i];
        s += a.x * a.x + a.y * a.y + a.z * a.z + a.w * a.w;
    }
    out[row] = s;
}

// ---------------------------------------------------------------------------
// C = max(x2 + y2 - 2*XP@XQ^T, 0); also global max via atomicMax on bits.
// 128x128 tile per block, 256 threads, 8x8 micro-tile (16-interleaved so
// smem reads are conflict-free with stride 33) , K staged 32 at a time.
// ---------------------------------------------------------------------------
__global__ void __launch_bounds__(256) gemm_kernel(const float* __restrict__ XP,
                                                   const float* __restrict__ XQ) {
    __shared__ float As[128][33];
    __shared__ float Bs[128][33];
    const int tx = threadIdx.x, ty = threadIdx.y;
    const int tid = ty * 16 + tx;
    const int bm = blockIdx.y, bn = blockIdx.x;

    float acc[8][8];
#pragma unroll
    for (int i = 0; i < 8; i++)
#pragma unroll
        for (int j = 0; j < 8; j++) acc[i][j] = 0.0f;

    for (int ks = 0; ks < DD; ks += 32) {
        // load 128x32 fp32 tiles of A and B (float4 global loads)
#pragma unroll
        for (int it = 0; it < 4; it++) {
            int r = (tid >> 3) + 32 * it;
            int f = tid & 7;
            float4 a4 = *(const float4*)(XP + (size_t)(bm * 128 + r) * DD + ks + f * 4);
            As[r][f * 4 + 0] = a4.x; As[r][f * 4 + 1] = a4.y;
            As[r][f * 4 + 2] = a4.z; As[r][f * 4 + 3] = a4.w;
            float4 b4 = *(const float4*)(XQ + (size_t)(bn * 128 + r) * DD + ks + f * 4);
            Bs[r][f * 4 + 0] = b4.x; Bs[r][f * 4 + 1] = b4.y;
            Bs[r][f * 4 + 2] = b4.z; Bs[r][f * 4 + 3] = b4.w;
        }
        __syncthreads();
#pragma unroll 4
        for (int kk = 0; kk < 32; kk++) {
            float a[8], b[8];
#pragma unroll
            for (int i = 0; i < 8; i++) a[i] = As[ty + 16 * i][kk];
#pragma unroll
            for (int j = 0; j < 8; j++) b[j] = Bs[tx + 16 * j][kk];
#pragma unroll
            for (int i = 0; i < 8; i++)
#pragma unroll
                for (int j = 0; j < 8; j++) acc[i][j] += a[i] * b[j];
        }
        __syncthreads();
    }

    float xr[8], yc[8];
#pragma unroll
    for (int i = 0; i < 8; i++) xr[i] = g_x2[bm * 128 + ty + 16 * i];
#pragma unroll
    for (int j = 0; j < 8; j++) yc[j] = g_y2[bn * 128 + tx + 16 * j];

    float lmax = 0.0f;
#pragma unroll
    for (int i = 0; i < 8; i++) {
        int row = bm * 128 + ty + 16 * i;
        float* Crow = g_C + (size_t)row * NN + bn * 128;
#pragma unroll
        for (int j = 0; j < 8; j++) {
            float c = xr[i] + yc[j] - 2.0f * acc[i][j];
            c = fmaxf(c, 0.0f);
            Crow[tx + 16 * j] = c;
            lmax = fmaxf(lmax, c);
        }
    }

    __shared__ float red[256];
    red[tid] = lmax;
    __syncthreads();
    for (int s = 128; s > 0; s >>= 1) {
        if (tid < s) red[tid] = fmaxf(red[tid], red[tid + s]);
        __syncthreads();
    }
    if (tid == 0) atomicMax(&g_cmax_bits, __float_as_uint(red[0]));  // order-independent
}

// ---------------------------------------------------------------------------
// K = exp(-C / (reg * Cmax))
// ---------------------------------------------------------------------------
__global__ void exp_kernel() {
    float cmax = __uint_as_float(g_cmax_bits);
    float s = -1.0f / (REG_E * cmax);
    const float4* C4 = (const float4*)g_C;
    float4* K4 = (float4*)g_K;
    int total = NN * (NN / 4);
    int stride = gridDim.x * blockDim.x;
    for (int i = blockIdx.x * blockDim.x + threadIdx.x; i < total; i += stride) {
        float4 c = C4[i];
        float4 k;
        k.x = __expf(c.x * s);
        k.y = __expf(c.y * s);
        k.z = __expf(c.z * s);
        k.w = __expf(c.w * s);
        K4[i] = k;
    }
}

// ---------------------------------------------------------------------------
// u_i = a / sum_j K_ij * v_j  — one warp per row, float4, warp shuffle reduce
// ---------------------------------------------------------------------------
__global__ void __launch_bounds__(256) row_kernel() {
    int gw = (blockIdx.x * 256 + threadIdx.x) >> 5;   // row
    int lane = threadIdx.x & 31;
    const float4* Kr = (const float4*)(g_K + (size_t)gw * NN);
    const float4* v4 = (const float4*)g_v;
    float acc = 0.0f;
#pragma unroll 4
    for (int j = lane; j < NN / 4; j += 32) {
        float4 k = Kr[j];
        float4 vv = v4[j];
        acc += k.x * vv.x + k.y * vv.y + k.z * vv.z + k.w * vv.w;
    }
#pragma unroll
    for (int off = 16; off; off >>= 1) acc += __shfl_xor_sync(0xffffffffu, acc, off);
    if (lane == 0) g_u[gw] = INVN / acc;
}

// ---------------------------------------------------------------------------
// column partials: cpart[chunk][j] = sum_{i in chunk} K_ij * u_i
// Deterministic (fixed partition, no float atomics).
// ---------------------------------------------------------------------------
__global__ void __launch_bounds__(256) col_kernel() {
    int c4 = blockIdx.x * 256 + threadIdx.x;          // float4 column index
    int r0 = blockIdx.y * ROWS_PER_CHUNK;
    const float4* K4 = (const float4*)g_K;
    float4 acc = make_float4(0.f, 0.f, 0.f, 0.f);
#pragma unroll 4
    for (int i = 0; i < ROWS_PER_CHUNK; i++) {
        float u = g_u[r0 + i];
        float4 k = K4[(size_t)(r0 + i) * (NN / 4) + c4];
        acc.x += k.x * u; acc.y += k.y * u;
        acc.z += k.z * u; acc.w += k.w * u;
    }
    ((float4*)g_cpart[blockIdx.y])[c4] = acc;
}

// v_j = b / sum_chunk cpart[chunk][j]
__global__ void vred_kernel() {
    int j = blockIdx.x * blockDim.x + threadIdx.x;
    float s = 0.0f;
#pragma unroll 8
    for (int ch = 0; ch < RCHUNK; ch++) s += g_cpart[ch][j];
    g_v[j] = INVN / s;
}

// ---------------------------------------------------------------------------
// result = sum_ij C_ij * u_i * K_ij * v_j — fixed-partition two-stage reduce
// ---------------------------------------------------------------------------
__global__ void __launch_bounds__(256) final_kernel() {
    const int per_block = (NN / 4) * NN / FINAL_BLOCKS;   // 8192 float4 = 4 rows
    int base = blockIdx.x * per_block;
    const float4* C4 = (const float4*)g_C;
    const float4* K4 = (const float4*)g_K;
    const float4* v4 = (const float4*)g_v;
    float acc = 0.0f;
    for (int t = threadIdx.x; t < per_block; t += 256) {
        int i4 = base + t;
        int row = i4 >> 11;          // 2048 float4 per row
        int c4 = i4 & 2047;
        float4 c = C4[i4];
        float4 k = K4[i4];
        float4 vv = v4[c4];
        float u = g_u[row];
        acc += u * (c.x * k.x * vv.x + c.y * k.y * vv.y +
                    c.z * k.z * vv.z + c.w * k.w * vv.w);
    }
    __shared__ float red[256];
    red[threadIdx.x] = acc;
    __syncthreads();
    for (int s = 128; s > 0; s >>= 1) {
        if (threadIdx.x < s) red[threadIdx.x] += red[threadIdx.x + s];
        __syncthreads();
    }
    if (threadIdx.x == 0) g_partial[blockIdx.x] = red[0];
}

__global__ void final_reduce_kernel(float* __restrict__ out) {
    __shared__ float red[256];
    float s = 0.0f;
    for (int i = threadIdx.x; i < FINAL_BLOCKS; i += 256) s += g_partial[i];
    red[threadIdx.x] = s;
    __syncthreads();
    for (int st = 128; st > 0; st >>= 1) {
        if (threadIdx.x < st) red[threadIdx.x] += red[threadIdx.x + st];
        __syncthreads();
    }
    if (threadIdx.x == 0) out[0] = red[0];
}

// ---------------------------------------------------------------------------
extern "C" void kernel_launch(void* const* d_in, const int* in_sizes, int n_in,
                              void* d_out, int out_size) {
    const float* XP = (const float*)d_in[0];
    const float* XQ = (const float*)d_in[1];
    float* out = (float*)d_out;

    init_kernel<<<NN / 256, 256>>>();
    norms_kernel<<<dim3(NN / 256, 2), 256>>>(XP, XQ);
    gemm_kernel<<<dim3(NN / 128, NN / 128), dim3(16, 16)>>>(XP, XQ);
    exp_kernel<<<8192, 256>>>();

    for (int it = 0; it < NITER; it++) {
        row_kernel<<<NN * 32 / 256, 256>>>();               // 1024 blocks
        col_kernel<<<dim3(NN / 4 / 256, RCHUNK), 256>>>();  // (8, 64)
        vred_kernel<<<NN / 256, 256>>>();
    }

    final_kernel<<<FINAL_BLOCKS, 256>>>();
    final_reduce_kernel<<<1, 256>>>(out);
}

// round 6
// speedup vs baseline: 1.3924x; 1.3924x over previous
#include <cuda_runtime.h>
#include <cuda_fp16.h>

// Problem constants (fixed by reference setup_inputs)
#define NN 8192
#define DD 64
#define NITER 20
#define REG_E 0.05f
#define INVN (1.0f / 8192.0f)
#define ALPHA 32768.0f   // fp16 scale for K; cancels exactly in Sinkhorn

#define RCHUNK 64
#define ROWS_PER_CHUNK (NN / RCHUNK)   // 128
#define FINAL_BLOCKS 2048

// Scratch: __device__ globals (no allocation allowed in kernel_launch)
__device__ float  g_C[(size_t)NN * NN];     // 256 MB cost matrix (fp32)
__device__ __half g_K16[(size_t)NN * NN];   // 128 MB Gibbs kernel alpha*exp(-C*s)
__device__ float g_x2[NN];
__device__ float g_y2[NN];
__device__ float g_u[NN];                   // stores u/alpha (scale cancels)
__device__ float g_v[NN];
__device__ unsigned g_cmax_bits;
__device__ float g_cpart[RCHUNK][NN];       // 2 MB column partial sums
__device__ float g_partial[FINAL_BLOCKS];

// ---------------------------------------------------------------------------
__global__ void init_kernel() {
    int j = blockIdx.x * blockDim.x + threadIdx.x;
    if (j < NN) g_v[j] = 1.0f;
    if (j == 0) g_cmax_bits = 0u;
}

// ---------------------------------------------------------------------------
__global__ void norms_kernel(const float* __restrict__ XP,
                             const float* __restrict__ XQ) {
    int row = blockIdx.x * blockDim.x + threadIdx.x;
    if (row >= NN) return;
    const float* X = blockIdx.y ? XQ : XP;
    float* out = blockIdx.y ? g_y2 : g_x2;
    const float4* p = (const float4*)(X + (size_t)row * DD);
    float s = 0.0f;
#pragma unroll
    for (int i = 0; i < DD / 4; i++) {
        float4 a = p[i];
        s += a.x * a.x + a.y * a.y + a.z * a.z + a.w * a.w;
    }
    out[row] = s;
}

// ---------------------------------------------------------------------------
// C = max(x2 + y2 - 2*XP@XQ^T, 0); global max via atomicMax on bits.
// ---------------------------------------------------------------------------
__global__ void __launch_bounds__(256) gemm_kernel(const float* __restrict__ XP,
                                                   const float* __restrict__ XQ) {
    __shared__ float As[128][33];
    __shared__ float Bs[128][33];
    const int tx = threadIdx.x, ty = threadIdx.y;
    const int tid = ty * 16 + tx;
    const int bm = blockIdx.y, bn = blockIdx.x;

    float acc[8][8];
#pragma unroll
    for (int i = 0; i < 8; i++)
#pragma unroll
        for (int j = 0; j < 8; j++) acc[i][j] = 0.0f;

    for (int ks = 0; ks < DD; ks += 32) {
#pragma unroll
        for (int it = 0; it < 4; it++) {
            int r = (tid >> 3) + 32 * it;
            int f = tid & 7;
            float4 a4 = *(const float4*)(XP + (size_t)(bm * 128 + r) * DD + ks + f * 4);
            As[r][f * 4 + 0] = a4.x; As[r][f * 4 + 1] = a4.y;
            As[r][f * 4 + 2] = a4.z; As[r][f * 4 + 3] = a4.w;
            float4 b4 = *(const float4*)(XQ + (size_t)(bn * 128 + r) * DD + ks + f * 4);
            Bs[r][f * 4 + 0] = b4.x; Bs[r][f * 4 + 1] = b4.y;
            Bs[r][f * 4 + 2] = b4.z; Bs[r][f * 4 + 3] = b4.w;
        }
        __syncthreads();
#pragma unroll 4
        for (int kk = 0; kk < 32; kk++) {
            float a[8], b[8];
#pragma unroll
            for (int i = 0; i < 8; i++) a[i] = As[ty + 16 * i][kk];
#pragma unroll
            for (int j = 0; j < 8; j++) b[j] = Bs[tx + 16 * j][kk];
#pragma unroll
            for (int i = 0; i < 8; i++)
#pragma unroll
                for (int j = 0; j < 8; j++) acc[i][j] += a[i] * b[j];
        }
        __syncthreads();
    }

    float xr[8], yc[8];
#pragma unroll
    for (int i = 0; i < 8; i++) xr[i] = g_x2[bm * 128 + ty + 16 * i];
#pragma unroll
    for (int j = 0; j < 8; j++) yc[j] = g_y2[bn * 128 + tx + 16 * j];

    float lmax = 0.0f;
#pragma unroll
    for (int i = 0; i < 8; i++) {
        int row = bm * 128 + ty + 16 * i;
        float* Crow = g_C + (size_t)row * NN + bn * 128;
#pragma unroll
        for (int j = 0; j < 8; j++) {
            float c = xr[i] + yc[j] - 2.0f * acc[i][j];
            c = fmaxf(c, 0.0f);
            Crow[tx + 16 * j] = c;
            lmax = fmaxf(lmax, c);
        }
    }

    __shared__ float red[256];
    red[tid] = lmax;
    __syncthreads();
    for (int s = 128; s > 0; s >>= 1) {
        if (tid < s) red[tid] = fmaxf(red[tid], red[tid + s]);
        __syncthreads();
    }
    if (tid == 0) atomicMax(&g_cmax_bits, __float_as_uint(red[0]));
}

// ---------------------------------------------------------------------------
// K16 = alpha * exp(-C / (reg * Cmax)); 8 elems/thread, 16B stores
// ---------------------------------------------------------------------------
__global__ void exp_kernel() {
    float cmax = __uint_as_float(g_cmax_bits);
    float s = -1.0f / (REG_E * cmax);
    const float4* C4 = (const float4*)g_C;
    uint4* K8 = (uint4*)g_K16;
    int total8 = NN * (NN / 8);
    int stride = gridDim.x * blockDim.x;
    for (int i = blockIdx.x * blockDim.x + threadIdx.x; i < total8; i += stride) {
        float4 c0 = C4[2 * i];
        float4 c1 = C4[2 * i + 1];
        __half2 h0 = __floats2half2_rn(__expf(c0.x * s) * ALPHA, __expf(c0.y * s) * ALPHA);
        __half2 h1 = __floats2half2_rn(__expf(c0.z * s) * ALPHA, __expf(c0.w * s) * ALPHA);
        __half2 h2 = __floats2half2_rn(__expf(c1.x * s) * ALPHA, __expf(c1.y * s) * ALPHA);
        __half2 h3 = __floats2half2_rn(__expf(c1.z * s) * ALPHA, __expf(c1.w * s) * ALPHA);
        uint4 o;
        o.x = *(unsigned*)&h0; o.y = *(unsigned*)&h1;
        o.z = *(unsigned*)&h2; o.w = *(unsigned*)&h3;
        K8[i] = o;
    }
}

// ---------------------------------------------------------------------------
// u' = (a/alpha) / sum_j K_ij v_j  — one warp per row, fp16 K, fp32 accum
// ---------------------------------------------------------------------------
__global__ void __launch_bounds__(256) row_kernel() {
    int row = (blockIdx.x * 256 + threadIdx.x) >> 5;
    int lane = threadIdx.x & 31;
    const uint4* Kr = (const uint4*)(g_K16 + (size_t)row * NN);  // 1024 uint4/row
    const float4* v4 = (const float4*)g_v;
    float acc = 0.0f;
#pragma unroll 4
    for (int j = lane; j < NN / 8; j += 32) {
        uint4 kk = Kr[j];
        float4 va = v4[2 * j], vb = v4[2 * j + 1];
        float2 f0 = __half22float2(*(__half2*)&kk.x);
        float2 f1 = __half22float2(*(__half2*)&kk.y);
        float2 f2 = __half22float2(*(__half2*)&kk.z);
        float2 f3 = __half22float2(*(__half2*)&kk.w);
        acc += f0.x * va.x + f0.y * va.y + f1.x * va.z + f1.y * va.w +
               f2.x * vb.x + f2.y * vb.y + f3.x * vb.z + f3.y * vb.w;
    }
#pragma unroll
    for (int off = 16; off; off >>= 1) acc += __shfl_xor_sync(0xffffffffu, acc, off);
    if (lane == 0) g_u[row] = INVN / acc;   // = u/alpha automatically
}

// ---------------------------------------------------------------------------
// column partials: cpart[chunk][j] = sum_{i in chunk} K_ij * u'_i
// (u' = u/alpha so this equals (K^T u)_j exactly). Deterministic partition.
// ---------------------------------------------------------------------------
__global__ void __launch_bounds__(256) col_kernel() {
    int c8 = blockIdx.x * 256 + threadIdx.x;          // 8-column group, 0..1023
    int r0 = blockIdx.y * ROWS_PER_CHUNK;
    const uint4* K8 = (const uint4*)g_K16;            // row stride 1024 uint4
    float acc[8];
#pragma unroll
    for (int k = 0; k < 8; k++) acc[k] = 0.0f;
#pragma unroll 4
    for (int i = 0; i < ROWS_PER_CHUNK; i++) {
        float u = g_u[r0 + i];
        uint4 kk = K8[(size_t)(r0 + i) * (NN / 8) + c8];
        float2 f0 = __half22float2(*(__half2*)&kk.x);
        float2 f1 = __half22float2(*(__half2*)&kk.y);
        float2 f2 = __half22float2(*(__half2*)&kk.z);
        float2 f3 = __half22float2(*(__half2*)&kk.w);
        acc[0] += f0.x * u; acc[1] += f0.y * u;
        acc[2] += f1.x * u; acc[3] += f1.y * u;
        acc[4] += f2.x * u; acc[5] += f2.y * u;
        acc[6] += f3.x * u; acc[7] += f3.y * u;
    }
    float4* out = (float4*)(g_cpart[blockIdx.y] + c8 * 8);
    out[0] = make_float4(acc[0], acc[1], acc[2], acc[3]);
    out[1] = make_float4(acc[4], acc[5], acc[6], acc[7]);
}

// v_j = b / sum_chunk cpart[chunk][j]
__global__ void vred_kernel() {
    int j = blockIdx.x * blockDim.x + threadIdx.x;
    float s = 0.0f;
#pragma unroll 8
    for (int ch = 0; ch < RCHUNK; ch++) s += g_cpart[ch][j];
    g_v[j] = INVN / s;
}

// ---------------------------------------------------------------------------
// result = sum_ij C_ij * u'_i * K16_ij * v_j  (= C .* plan exactly)
// ---------------------------------------------------------------------------
__global__ void __launch_bounds__(256) final_kernel() {
    const int per_block = (NN / 8) * NN / FINAL_BLOCKS;   // 4096 groups of 8
    int base = blockIdx.x * per_block;
    const float4* C4 = (const float4*)g_C;
    const uint4* K8 = (const uint4*)g_K16;
    const float4* v4 = (const float4*)g_v;
    float acc = 0.0f;
    for (int t = threadIdx.x; t < per_block; t += 256) {
        int e8 = base + t;
        int row = e8 >> 10;          // 1024 groups of 8 per row
        int c8 = e8 & 1023;
        uint4 kk = K8[e8];
        float4 c0 = C4[2 * e8], c1 = C4[2 * e8 + 1];
        float4 va = v4[2 * c8], vb = v4[2 * c8 + 1];
        float u = g_u[row];
        float2 f0 = __half22float2(*(__half2*)&kk.x);
        float2 f1 = __half22float2(*(__half2*)&kk.y);
        float2 f2 = __half22float2(*(__half2*)&kk.z);
        float2 f3 = __half22float2(*(__half2*)&kk.w);
        acc += u * (c0.x * f0.x * va.x + c0.y * f0.y * va.y +
                    c0.z * f1.x * va.z + c0.w * f1.y * va.w +
                    c1.x * f2.x * vb.x + c1.y * f2.y * vb.y +
                    c1.z * f3.x * vb.z + c1.w * f3.y * vb.w);
    }
    __shared__ float red[256];
    red[threadIdx.x] = acc;
    __syncthreads();
    for (int s = 128; s > 0; s >>= 1) {
        if (threadIdx.x < s) red[threadIdx.x] += red[threadIdx.x + s];
        __syncthreads();
    }
    if (threadIdx.x == 0) g_partial[blockIdx.x] = red[0];
}

__global__ void final_reduce_kernel(float* __restrict__ out) {
    __shared__ float red[256];
    float s = 0.0f;
    for (int i = threadIdx.x; i < FINAL_BLOCKS; i += 256) s += g_partial[i];
    red[threadIdx.x] = s;
    __syncthreads();
    for (int st = 128; st > 0; st >>= 1) {
        if (threadIdx.x < st) red[threadIdx.x] += red[threadIdx.x + st];
        __syncthreads();
    }
    if (threadIdx.x == 0) out[0] = red[0];
}

// ---------------------------------------------------------------------------
extern "C" void kernel_launch(void* const* d_in, const int* in_sizes, int n_in,
                              void* d_out, int out_size) {
    const float* XP = (const float*)d_in[0];
    const float* XQ = (const float*)d_in[1];
    float* out = (float*)d_out;

    init_kernel<<<NN / 256, 256>>>();
    norms_kernel<<<dim3(NN / 256, 2), 256>>>(XP, XQ);
    gemm_kernel<<<dim3(NN / 128, NN / 128), dim3(16, 16)>>>(XP, XQ);
    exp_kernel<<<8192, 256>>>();

    for (int it = 0; it < NITER; it++) {
        row_kernel<<<NN * 32 / 256, 256>>>();               // 1024 blocks
        col_kernel<<<dim3(NN / 8 / 256, RCHUNK), 256>>>();  // (4, 64)
        vred_kernel<<<NN / 256, 256>>>();
    }

    final_kernel<<<FINAL_BLOCKS, 256>>>();
    final_reduce_kernel<<<1, 256>>>(out);
}

// round 8
// speedup vs baseline: 1.5928x; 1.1439x over previous
#include <cuda_runtime.h>
#include <cuda_fp16.h>

// Problem constants (fixed by reference setup_inputs)
#define NN 8192
#define DD 64
#define NITER 20
#define REG_E 0.05f
#define INVN (1.0f / 8192.0f)
#define ALPHA 32768.0f           // fp16 scale for K; cancels exactly in Sinkhorn
#define LN_ALPHA 10.397207708399179f  // ln(2^15)

#define RCHUNK 64
#define ROWS_PER_CHUNK (NN / RCHUNK)   // 128
#define FINAL_BLOCKS 2048

// Single 128 MB fp16 buffer: holds C16 after GEMM, overwritten in-place with
// K16 = ALPHA*exp(-C/(reg*cmax)) by exp_kernel.
__device__ __half g_K16[(size_t)NN * NN];
__device__ float g_x2[NN];
__device__ float g_y2[NN];
__device__ float g_u[NN];                 // stores u/ALPHA (scale cancels)
__device__ float g_v[NN];
__device__ unsigned g_cmax_bits;
__device__ float g_cpart[RCHUNK][NN];     // 2 MB column partial sums
__device__ float g_partial[FINAL_BLOCKS];

// ---------------------------------------------------------------------------
__global__ void init_kernel() {
    int j = blockIdx.x * blockDim.x + threadIdx.x;
    if (j < NN) g_v[j] = 1.0f;
    if (j == 0) g_cmax_bits = 0u;
}

// ---------------------------------------------------------------------------
__global__ void norms_kernel(const float* __restrict__ XP,
                             const float* __restrict__ XQ) {
    int row = blockIdx.x * blockDim.x + threadIdx.x;
    if (row >= NN) return;
    const float* X = blockIdx.y ? XQ : XP;
    float* out = blockIdx.y ? g_y2 : g_x2;
    const float4* p = (const float4*)(X + (size_t)row * DD);
    float s = 0.0f;
#pragma unroll
    for (int i = 0; i < DD / 4; i++) {
        float4 a = p[i];
        s += a.x * a.x + a.y * a.y + a.z * a.z + a.w * a.w;
    }
    out[row] = s;
}

// ---------------------------------------------------------------------------
// Tensor-core GEMM: C = max(x2 + y2 - 2*XP@XQ^T, 0) stored as fp16.
// mma.sync m16n8k16 f16 inputs, f32 accumulate. 128x128 block tile, 8 warps
// (2x4), 64x32 warp tile, K=64 fully staged. SMEM stride 72 halves ->
// 32-bit word bank index = (4g + t + const) % 32 : conflict-free frags.
// ---------------------------------------------------------------------------
#define SROW 72
__global__ void __launch_bounds__(256) gemm_kernel(const float* __restrict__ XP,
                                                   const float* __restrict__ XQ) {
    __shared__ __half As[128 * SROW];   // 18432 B
    __shared__ __half Bs[128 * SROW];   // 18432 B
    __shared__ float red[256];

    const int tid = threadIdx.x;
    const int warp = tid >> 5, lane = tid & 31;
    const int wm = warp >> 2, wn = warp & 3;     // 2 x 4 warp grid
    const int g = lane >> 2, t = lane & 3;
    const int bm = blockIdx.y, bn = blockIdx.x;

    // Load 128x64 fp32 tiles -> fp16 smem (8 float4 per thread per tensor)
#pragma unroll
    for (int i = 0; i < 8; i++) {
        int idx = i * 256 + tid;          // 0..2047
        int r = idx >> 4;                 // 16 float4 per row
        int c4 = idx & 15;
        float4 a = *(const float4*)(XP + (size_t)(bm * 128 + r) * DD + c4 * 4);
        __half2 a01 = __floats2half2_rn(a.x, a.y);
        __half2 a23 = __floats2half2_rn(a.z, a.w);
        uint2 pa; pa.x = *(unsigned*)&a01; pa.y = *(unsigned*)&a23;
        *(uint2*)(As + r * SROW + c4 * 4) = pa;
        float4 b = *(const float4*)(XQ + (size_t)(bn * 128 + r) * DD + c4 * 4);
        __half2 b01 = __floats2half2_rn(b.x, b.y);
        __half2 b23 = __floats2half2_rn(b.z, b.w);
        uint2 pb; pb.x = *(unsigned*)&b01; pb.y = *(unsigned*)&b23;
        *(uint2*)(Bs + r * SROW + c4 * 4) = pb;
    }
    __syncthreads();

    float acc[4][4][4];
#pragma unroll
    for (int mt = 0; mt < 4; mt++)
#pragma unroll
        for (int nt = 0; nt < 4; nt++)
#pragma unroll
            for (int r = 0; r < 4; r++) acc[mt][nt][r] = 0.0f;

#pragma unroll
    for (int ks = 0; ks < 4; ks++) {
        const int k0 = ks * 16;
        unsigned af[4][4], bf[4][2];
#pragma unroll
        for (int mt = 0; mt < 4; mt++) {
            int row = wm * 64 + mt * 16;
            af[mt][0] = *(unsigned*)(As + (row + g) * SROW + k0 + 2 * t);
            af[mt][1] = *(unsigned*)(As + (row + g + 8) * SROW + k0 + 2 * t);
            af[mt][2] = *(unsigned*)(As + (row + g) * SROW + k0 + 2 * t + 8);
            af[mt][3] = *(unsigned*)(As + (row + g + 8) * SROW + k0 + 2 * t + 8);
        }
#pragma unroll
        for (int nt = 0; nt < 4; nt++) {
            int col = wn * 32 + nt * 8 + g;
            bf[nt][0] = *(unsigned*)(Bs + col * SROW + k0 + 2 * t);
            bf[nt][1] = *(unsigned*)(Bs + col * SROW + k0 + 2 * t + 8);
        }
#pragma unroll
        for (int mt = 0; mt < 4; mt++)
#pragma unroll
            for (int nt = 0; nt < 4; nt++) {
                asm volatile(
                    "mma.sync.aligned.m16n8k16.row.col.f32.f16.f16.f32 "
                    "{%0,%1,%2,%3},{%4,%5,%6,%7},{%8,%9},{%0,%1,%2,%3};\n"
                    : "+f"(acc[mt][nt][0]), "+f"(acc[mt][nt][1]),
                      "+f"(acc[mt][nt][2]), "+f"(acc[mt][nt][3])
                    : "r"(af[mt][0]), "r"(af[mt][1]), "r"(af[mt][2]), "r"(af[mt][3]),
                      "r"(bf[nt][0]), "r"(bf[nt][1]));
            }
    }

    // Epilogue: C = max(x2 + y2 - 2*acc, 0) -> fp16 (half2 stores); track max
    float lmax = 0.0f;
#pragma unroll
    for (int mt = 0; mt < 4; mt++) {
        int r0 = bm * 128 + wm * 64 + mt * 16 + g;
        float xA = g_x2[r0], xB = g_x2[r0 + 8];
#pragma unroll
        for (int nt = 0; nt < 4; nt++) {
            int c0 = bn * 128 + wn * 32 + nt * 8 + 2 * t;
            float y0 = g_y2[c0], y1 = g_y2[c0 + 1];
            float v00 = fmaxf(xA + y0 - 2.0f * acc[mt][nt][0], 0.0f);
            float v01 = fmaxf(xA + y1 - 2.0f * acc[mt][nt][1], 0.0f);
            float v10 = fmaxf(xB + y0 - 2.0f * acc[mt][nt][2], 0.0f);
            float v11 = fmaxf(xB + y1 - 2.0f * acc[mt][nt][3], 0.0f);
            lmax = fmaxf(lmax, fmaxf(fmaxf(v00, v01), fmaxf(v10, v11)));
            *(__half2*)(g_K16 + (size_t)r0 * NN + c0) = __floats2half2_rn(v00, v01);
            *(__half2*)(g_K16 + (size_t)(r0 + 8) * NN + c0) = __floats2half2_rn(v10, v11);
        }
    }

    red[tid] = lmax;
    __syncthreads();
    for (int s = 128; s > 0; s >>= 1) {
        if (tid < s) red[tid] = fmaxf(red[tid], red[tid + s]);
        __syncthreads();
    }
    if (tid == 0) atomicMax(&g_cmax_bits, __float_as_uint(red[0]));
}

// ---------------------------------------------------------------------------
// In-place: K16 = ALPHA * exp(-C16 / (reg * Cmax)); 8 halves per thread
// ---------------------------------------------------------------------------
__global__ void exp_kernel() {
    float cmax = __uint_as_float(g_cmax_bits);
    float s = -1.0f / (REG_E * cmax);
    uint4* K8 = (uint4*)g_K16;
    int total8 = NN * (NN / 8);
    int stride = gridDim.x * blockDim.x;
    for (int i = blockIdx.x * blockDim.x + threadIdx.x; i < total8; i += stride) {
        uint4 c = K8[i];
        float2 c0 = __half22float2(*(__half2*)&c.x);
        float2 c1 = __half22float2(*(__half2*)&c.y);
        float2 c2 = __half22float2(*(__half2*)&c.z);
        float2 c3 = __half22float2(*(__half2*)&c.w);
        __half2 h0 = __floats2half2_rn(__expf(c0.x * s) * ALPHA, __expf(c0.y * s) * ALPHA);
        __half2 h1 = __floats2half2_rn(__expf(c1.x * s) * ALPHA, __expf(c1.y * s) * ALPHA);
        __half2 h2 = __floats2half2_rn(__expf(c2.x * s) * ALPHA, __expf(c2.y * s) * ALPHA);
        __half2 h3 = __floats2half2_rn(__expf(c3.x * s) * ALPHA, __expf(c3.y * s) * ALPHA);
        uint4 o;
        o.x = *(unsigned*)&h0; o.y = *(unsigned*)&h1;
        o.z = *(unsigned*)&h2; o.w = *(unsigned*)&h3;
        K8[i] = o;
    }
}

// ---------------------------------------------------------------------------
// u' = (a/ALPHA) / sum_j K_ij v_j — one warp per row, fp16 K, fp32 accum
// ---------------------------------------------------------------------------
__global__ void __launch_bounds__(256) row_kernel() {
    int row = (blockIdx.x * 256 + threadIdx.x) >> 5;
    int lane = threadIdx.x & 31;
    const uint4* Kr = (const uint4*)(g_K16 + (size_t)row * NN);  // 1024 uint4/row
    const float4* v4 = (const float4*)g_v;
    float acc = 0.0f;
#pragma unroll 4
    for (int j = lane; j < NN / 8; j += 32) {
        uint4 kk = Kr[j];
        float4 va = v4[2 * j], vb = v4[2 * j + 1];
        float2 f0 = __half22float2(*(__half2*)&kk.x);
        float2 f1 = __half22float2(*(__half2*)&kk.y);
        float2 f2 = __half22float2(*(__half2*)&kk.z);
        float2 f3 = __half22float2(*(__half2*)&kk.w);
        acc += f0.x * va.x + f0.y * va.y + f1.x * va.z + f1.y * va.w +
               f2.x * vb.x + f2.y * vb.y + f3.x * vb.z + f3.y * vb.w;
    }
#pragma unroll
    for (int off = 16; off; off >>= 1) acc += __shfl_xor_sync(0xffffffffu, acc, off);
    if (lane == 0) g_u[row] = INVN / acc;   // = u/ALPHA automatically
}

// ---------------------------------------------------------------------------
// column partials: cpart[chunk][j] = sum_{i in chunk} K_ij * u'_i
// ---------------------------------------------------------------------------
__global__ void __launch_bounds__(256) col_kernel() {
    int c8 = blockIdx.x * 256 + threadIdx.x;          // 8-column group, 0..1023
    int r0 = blockIdx.y * ROWS_PER_CHUNK;
    const uint4* K8 = (const uint4*)g_K16;            // row stride 1024 uint4
    float acc[8];
#pragma unroll
    for (int k = 0; k < 8; k++) acc[k] = 0.0f;
#pragma unroll 4
    for (int i = 0; i < ROWS_PER_CHUNK; i++) {
        float u = g_u[r0 + i];
        uint4 kk = K8[(size_t)(r0 + i) * (NN / 8) + c8];
        float2 f0 = __half22float2(*(__half2*)&kk.x);
        float2 f1 = __half22float2(*(__half2*)&kk.y);
        float2 f2 = __half22float2(*(__half2*)&kk.z);
        float2 f3 = __half22float2(*(__half2*)&kk.w);
        acc[0] += f0.x * u; acc[1] += f0.y * u;
        acc[2] += f1.x * u; acc[3] += f1.y * u;
        acc[4] += f2.x * u; acc[5] += f2.y * u;
        acc[6] += f3.x * u; acc[7] += f3.y * u;
    }
    float4* out = (float4*)(g_cpart[blockIdx.y] + c8 * 8);
    out[0] = make_float4(acc[0], acc[1], acc[2], acc[3]);
    out[1] = make_float4(acc[4], acc[5], acc[6], acc[7]);
}

// v_j = b / sum_chunk cpart[chunk][j]
__global__ void vred_kernel() {
    int j = blockIdx.x * blockDim.x + threadIdx.x;
    float s = 0.0f;
#pragma unroll 8
    for (int ch = 0; ch < RCHUNK; ch++) s += g_cpart[ch][j];
    g_v[j] = INVN / s;
}

// ---------------------------------------------------------------------------
// result = sum_ij C_ij * plan_ij ; C recovered as (lnALPHA - ln K16)*reg*cmax
// ---------------------------------------------------------------------------
__global__ void __launch_bounds__(256) final_kernel() {
    const int per_block = (NN / 8) * NN / FINAL_BLOCKS;   // 4096 groups of 8
    int base = blockIdx.x * per_block;
    float sigma = REG_E * __uint_as_float(g_cmax_bits);
    const uint4* K8 = (const uint4*)g_K16;
    const float4* v4 = (const float4*)g_v;
    float acc = 0.0f;
    for (int t = threadIdx.x; t < per_block; t += 256) {
        int e8 = base + t;
        int row = e8 >> 10;          // 1024 groups of 8 per row
        int c8 = e8 & 1023;
        uint4 kk = K8[e8];
        float4 va = v4[2 * c8], vb = v4[2 * c8 + 1];
        float u = g_u[row];
        float2 f0 = __half22float2(*(__half2*)&kk.x);
        float2 f1 = __half22float2(*(__half2*)&kk.y);
        float2 f2 = __half22float2(*(__half2*)&kk.z);
        float2 f3 = __half22float2(*(__half2*)&kk.w);
        float s = 0.0f;
        s += f0.x * va.x * (LN_ALPHA - __logf(f0.x));
        s += f0.y * va.y * (LN_ALPHA - __logf(f0.y));
        s += f1.x * va.z * (LN_ALPHA - __logf(f1.x));
        s += f1.y * va.w * (LN_ALPHA - __logf(f1.y));
        s += f2.x * vb.x * (LN_ALPHA - __logf(f2.x));
        s += f2.y * vb.y * (LN_ALPHA - __logf(f2.y));
        s += f3.x * vb.z * (LN_ALPHA - __logf(f3.x));
        s += f3.y * vb.w * (LN_ALPHA - __logf(f3.y));
        acc += u * s;
    }
    acc *= sigma;
    __shared__ float red[256];
    red[threadIdx.x] = acc;
    __syncthreads();
    for (int s = 128; s > 0; s >>= 1) {
        if (threadIdx.x < s) red[threadIdx.x] += red[threadIdx.x + s];
        __syncthreads();
    }
    if (threadIdx.x == 0) g_partial[blockIdx.x] = red[0];
}

__global__ void final_reduce_kernel(float* __restrict__ out) {
    __shared__ float red[256];
    float s = 0.0f;
    for (int i = threadIdx.x; i < FINAL_BLOCKS; i += 256) s += g_partial[i];
    red[threadIdx.x] = s;
    __syncthreads();
    for (int st = 128; st > 0; st >>= 1) {
        if (threadIdx.x < st) red[threadIdx.x] += red[threadIdx.x + st];
        __syncthreads();
    }
    if (threadIdx.x == 0) out[0] = red[0];
}

// ---------------------------------------------------------------------------
extern "C" void kernel_launch(void* const* d_in, const int* in_sizes, int n_in,
                              void* d_out, int out_size) {
    const float* XP = (const float*)d_in[0];
    const float* XQ = (const float*)d_in[1];
    float* out = (float*)d_out;

    init_kernel<<<NN / 256, 256>>>();
    norms_kernel<<<dim3(NN / 256, 2), 256>>>(XP, XQ);
    gemm_kernel<<<dim3(NN / 128, NN / 128), 256>>>(XP, XQ);
    exp_kernel<<<8192, 256>>>();

    for (int it = 0; it < NITER; it++) {
        row_kernel<<<NN * 32 / 256, 256>>>();               // 1024 blocks
        col_kernel<<<dim3(NN / 8 / 256, RCHUNK), 256>>>();  // (4, 64)
        vred_kernel<<<NN / 256, 256>>>();
    }

    final_kernel<<<FINAL_BLOCKS, 256>>>();
    final_reduce_kernel<<<1, 256>>>(out);
}

// round 11
// speedup vs baseline: 1.9007x; 1.1933x over previous
#include <cuda_runtime.h>
#include <cuda_fp16.h>

// Problem constants (fixed by reference setup_inputs)
#define NN 8192
#define DD 64
#define NITER 20
#define REG_E 0.05f
#define INVN (1.0f / 8192.0f)
#define ALPHA 32768.0f                 // fp16 scale for K; cancels exactly
#define LN_ALPHA 10.397207708399179f   // ln(2^15)

#define FB 128                // fused blocks
#define FROWS (NN / FB)       // 64 rows per block
#define GR 4                  // rows per group
#define NG (FROWS / GR)       // 16 groups
#define GBYTES (GR * NN * 2)  // 65536 bytes per group tile
#define FUSED_SMEM (2 * GBYTES + 256)

#define FINAL_BLOCKS 2048

// Single 128 MB fp16 buffer: C16 after GEMM, overwritten in-place with
// K16 = ALPHA*exp(-C/(reg*cmax)) by exp_kernel.
__device__ __half g_K16[(size_t)NN * NN];
__device__ float g_x2[NN];
__device__ float g_y2[NN];
__device__ float g_u[NN];                 // stores u/ALPHA (scale cancels)
__device__ float g_v[NN];
__device__ unsigned g_cmax_bits;
__device__ float g_cpart[FB][NN];         // 4 MB column partial sums
__device__ float g_partial[FINAL_BLOCKS];

// ---------------------------------------------------------------------------
__global__ void init_kernel() {
    int j = blockIdx.x * blockDim.x + threadIdx.x;
    if (j < NN) g_v[j] = 1.0f;
    if (j == 0) g_cmax_bits = 0u;
}

// ---------------------------------------------------------------------------
__global__ void norms_kernel(const float* __restrict__ XP,
                             const float* __restrict__ XQ) {
    int row = blockIdx.x * blockDim.x + threadIdx.x;
    if (row >= NN) return;
    const float* X = blockIdx.y ? XQ : XP;
    float* out = blockIdx.y ? g_y2 : g_x2;
    const float4* p = (const float4*)(X + (size_t)row * DD);
    float s = 0.0f;
#pragma unroll
    for (int i = 0; i < DD / 4; i++) {
        float4 a = p[i];
        s += a.x * a.x + a.y * a.y + a.z * a.z + a.w * a.w;
    }
    out[row] = s;
}

// ---------------------------------------------------------------------------
// Tensor-core GEMM: C = max(x2 + y2 - 2*XP@XQ^T, 0) stored as fp16.
// ---------------------------------------------------------------------------
#define SROW 72
__global__ void __launch_bounds__(256) gemm_kernel(const float* __restrict__ XP,
                                                   const float* __restrict__ XQ) {
    __shared__ __half As[128 * SROW];
    __shared__ __half Bs[128 * SROW];
    __shared__ float red[256];

    const int tid = threadIdx.x;
    const int warp = tid >> 5, lane = tid & 31;
    const int wm = warp >> 2, wn = warp & 3;
    const int g = lane >> 2, t = lane & 3;
    const int bm = blockIdx.y, bn = blockIdx.x;

#pragma unroll
    for (int i = 0; i < 8; i++) {
        int idx = i * 256 + tid;
        int r = idx >> 4;
        int c4 = idx & 15;
        float4 a = *(const float4*)(XP + (size_t)(bm * 128 + r) * DD + c4 * 4);
        __half2 a01 = __floats2half2_rn(a.x, a.y);
        __half2 a23 = __floats2half2_rn(a.z, a.w);
        uint2 pa; pa.x = *(unsigned*)&a01; pa.y = *(unsigned*)&a23;
        *(uint2*)(As + r * SROW + c4 * 4) = pa;
        float4 b = *(const float4*)(XQ + (size_t)(bn * 128 + r) * DD + c4 * 4);
        __half2 b01 = __floats2half2_rn(b.x, b.y);
        __half2 b23 = __floats2half2_rn(b.z, b.w);
        uint2 pb; pb.x = *(unsigned*)&b01; pb.y = *(unsigned*)&b23;
        *(uint2*)(Bs + r * SROW + c4 * 4) = pb;
    }
    __syncthreads();

    float acc[4][4][4];
#pragma unroll
    for (int mt = 0; mt < 4; mt++)
#pragma unroll
        for (int nt = 0; nt < 4; nt++)
#pragma unroll
            for (int r = 0; r < 4; r++) acc[mt][nt][r] = 0.0f;

#pragma unroll
    for (int ks = 0; ks < 4; ks++) {
        const int k0 = ks * 16;
        unsigned af[4][4], bf[4][2];
#pragma unroll
        for (int mt = 0; mt < 4; mt++) {
            int row = wm * 64 + mt * 16;
            af[mt][0] = *(unsigned*)(As + (row + g) * SROW + k0 + 2 * t);
            af[mt][1] = *(unsigned*)(As + (row + g + 8) * SROW + k0 + 2 * t);
            af[mt][2] = *(unsigned*)(As + (row + g) * SROW + k0 + 2 * t + 8);
            af[mt][3] = *(unsigned*)(As + (row + g + 8) * SROW + k0 + 2 * t + 8);
        }
#pragma unroll
        for (int nt = 0; nt < 4; nt++) {
            int col = wn * 32 + nt * 8 + g;
            bf[nt][0] = *(unsigned*)(Bs + col * SROW + k0 + 2 * t);
            bf[nt][1] = *(unsigned*)(Bs + col * SROW + k0 + 2 * t + 8);
        }
#pragma unroll
        for (int mt = 0; mt < 4; mt++)
#pragma unroll
            for (int nt = 0; nt < 4; nt++) {
                asm volatile(
                    "mma.sync.aligned.m16n8k16.row.col.f32.f16.f16.f32 "
                    "{%0,%1,%2,%3},{%4,%5,%6,%7},{%8,%9},{%0,%1,%2,%3};\n"
                    : "+f"(acc[mt][nt][0]), "+f"(acc[mt][nt][1]),
                      "+f"(acc[mt][nt][2]), "+f"(acc[mt][nt][3])
                    : "r"(af[mt][0]), "r"(af[mt][1]), "r"(af[mt][2]), "r"(af[mt][3]),
                      "r"(bf[nt][0]), "r"(bf[nt][1]));
            }
    }

    float lmax = 0.0f;
#pragma unroll
    for (int mt = 0; mt < 4; mt++) {
        int r0 = bm * 128 + wm * 64 + mt * 16 + g;
        float xA = g_x2[r0], xB = g_x2[r0 + 8];
#pragma unroll
        for (int nt = 0; nt < 4; nt++) {
            int c0 = bn * 128 + wn * 32 + nt * 8 + 2 * t;
            float y0 = g_y2[c0], y1 = g_y2[c0 + 1];
            float v00 = fmaxf(xA + y0 - 2.0f * acc[mt][nt][0], 0.0f);
            float v01 = fmaxf(xA + y1 - 2.0f * acc[mt][nt][1], 0.0f);
            float v10 = fmaxf(xB + y0 - 2.0f * acc[mt][nt][2], 0.0f);
            float v11 = fmaxf(xB + y1 - 2.0f * acc[mt][nt][3], 0.0f);
            lmax = fmaxf(lmax, fmaxf(fmaxf(v00, v01), fmaxf(v10, v11)));
            *(__half2*)(g_K16 + (size_t)r0 * NN + c0) = __floats2half2_rn(v00, v01);
            *(__half2*)(g_K16 + (size_t)(r0 + 8) * NN + c0) = __floats2half2_rn(v10, v11);
        }
    }

    red[tid] = lmax;
    __syncthreads();
    for (int s = 128; s > 0; s >>= 1) {
        if (tid < s) red[tid] = fmaxf(red[tid], red[tid + s]);
        __syncthreads();
    }
    if (tid == 0) atomicMax(&g_cmax_bits, __float_as_uint(red[0]));
}

// ---------------------------------------------------------------------------
// In-place: K16 = ALPHA * exp(-C16 / (reg * Cmax))
// ---------------------------------------------------------------------------
__global__ void exp_kernel() {
    float cmax = __uint_as_float(g_cmax_bits);
    float s = -1.0f / (REG_E * cmax);
    uint4* K8 = (uint4*)g_K16;
    int total8 = NN * (NN / 8);
    int stride = gridDim.x * blockDim.x;
    for (int i = blockIdx.x * blockDim.x + threadIdx.x; i < total8; i += stride) {
        uint4 c = K8[i];
        float2 c0 = __half22float2(*(__half2*)&c.x);
        float2 c1 = __half22float2(*(__half2*)&c.y);
        float2 c2 = __half22float2(*(__half2*)&c.z);
        float2 c3 = __half22float2(*(__half2*)&c.w);
        __half2 h0 = __floats2half2_rn(__expf(c0.x * s) * ALPHA, __expf(c0.y * s) * ALPHA);
        __half2 h1 = __floats2half2_rn(__expf(c1.x * s) * ALPHA, __expf(c1.y * s) * ALPHA);
        __half2 h2 = __floats2half2_rn(__expf(c2.x * s) * ALPHA, __expf(c2.y * s) * ALPHA);
        __half2 h3 = __floats2half2_rn(__expf(c3.x * s) * ALPHA, __expf(c3.y * s) * ALPHA);
        uint4 o;
        o.x = *(unsigned*)&h0; o.y = *(unsigned*)&h1;
        o.z = *(unsigned*)&h2; o.w = *(unsigned*)&h3;
        K8[i] = o;
    }
}

// ---------------------------------------------------------------------------
// Fused Sinkhorn half-iteration pair: ONE pass over K per iteration.
// Block handles 64 rows in 16 double-buffered groups of 4 rows (64 KB tiles,
// TMA bulk copy -> SMEM). Per group:
//   Phase A: u_i = INVN / dot(K_i, v)   (2 warps per row, from SMEM)
//   Phase B: col partials += K_ij * u_i (thread-owned columns, reg accum)
// cpart[blk][:] written once at the end; vred_kernel folds 128 chunks -> v.
// ---------------------------------------------------------------------------
__global__ void __launch_bounds__(256) fused_kernel() {
    extern __shared__ __align__(128) unsigned char s_raw[];
    const int tid = threadIdx.x;
    const int blk = blockIdx.x;
    const int row0 = blk * FROWS;

    __half* buf0 = (__half*)s_raw;
    __half* buf1 = (__half*)(s_raw + GBYTES);
    float* sdot = (float*)(s_raw + 2 * GBYTES);            // [GR][2] = 8 floats
    float* su = sdot + 8;                                  // [GR]
    unsigned long long* mbar = (unsigned long long*)(sdot + 16);  // 2 mbarriers

    unsigned mbar_s[2], buf_s[2];
    mbar_s[0] = (unsigned)__cvta_generic_to_shared(&mbar[0]);
    mbar_s[1] = (unsigned)__cvta_generic_to_shared(&mbar[1]);
    buf_s[0] = (unsigned)__cvta_generic_to_shared(buf0);
    buf_s[1] = (unsigned)__cvta_generic_to_shared(buf1);
    const uint4* bufs4[2] = { (const uint4*)buf0, (const uint4*)buf1 };

    if (tid == 0) {
        asm volatile("mbarrier.init.shared.b64 [%0], 1;" :: "r"(mbar_s[0]) : "memory");
        asm volatile("mbarrier.init.shared.b64 [%0], 1;" :: "r"(mbar_s[1]) : "memory");
    }
    __syncthreads();

    float acc[4][8];
#pragma unroll
    for (int j = 0; j < 4; j++)
#pragma unroll
        for (int k = 0; k < 8; k++) acc[j][k] = 0.0f;

    // Prologue: issue group 0 into buffer 0
    if (tid == 0) {
        unsigned long long gsrc;
        const __half* src = g_K16 + (size_t)row0 * NN;
        asm volatile("cvta.to.global.u64 %0, %1;" : "=l"(gsrc) : "l"(src));
        asm volatile("mbarrier.arrive.expect_tx.shared.b64 _, [%0], %1;"
                     :: "r"(mbar_s[0]), "r"((unsigned)GBYTES) : "memory");
        asm volatile("cp.async.bulk.shared::cta.global.mbarrier::complete_tx::bytes "
                     "[%0], [%1], %2, [%3];"
                     :: "r"(buf_s[0]), "l"(gsrc), "r"((unsigned)GBYTES), "r"(mbar_s[0])
                     : "memory");
    }

    int phase0 = 0, phase1 = 0;
    const int warp = tid >> 5, lane = tid & 31;
    const int arow = warp >> 1, ahalf = warp & 1;
    const float4* v4 = (const float4*)g_v;

    for (int g = 0; g < NG; g++) {
        const int b = g & 1;
        // Issue next group into the other buffer (its readers synced out last group)
        if (tid == 0 && g + 1 < NG) {
            unsigned long long gsrc;
            const __half* src = g_K16 + (size_t)(row0 + (g + 1) * GR) * NN;
            asm volatile("cvta.to.global.u64 %0, %1;" : "=l"(gsrc) : "l"(src));
            asm volatile("mbarrier.arrive.expect_tx.shared.b64 _, [%0], %1;"
                         :: "r"(mbar_s[b ^ 1]), "r"((unsigned)GBYTES) : "memory");
            asm volatile("cp.async.bulk.shared::cta.global.mbarrier::complete_tx::bytes "
                         "[%0], [%1], %2, [%3];"
                         :: "r"(buf_s[b ^ 1]), "l"(gsrc), "r"((unsigned)GBYTES), "r"(mbar_s[b ^ 1])
                         : "memory");
        }
        // Wait for buffer b
        {
            int ph = b ? phase1 : phase0;
            unsigned done = 0;
            while (!done) {
                asm volatile(
                    "{\n\t.reg .pred p;\n\t"
                    "mbarrier.try_wait.parity.acquire.cta.shared::cta.b64 p, [%1], %2, 0x989680;\n\t"
                    "selp.b32 %0, 1, 0, p;\n\t}"
                    : "=r"(done) : "r"(mbar_s[b]), "r"(ph) : "memory");
            }
            if (b) phase1 ^= 1; else phase0 ^= 1;
        }

        const uint4* KU = bufs4[b];

        // ---- Phase A: row dots (2 warps per row, 512 uint4 per half-row)
        {
            const uint4* rowp = KU + arow * 1024 + ahalf * 512;
            float d = 0.0f;
#pragma unroll 8
            for (int k = 0; k < 16; k++) {
                int idx = lane + 32 * k;
                uint4 kk = rowp[idx];
                int vbase = 2 * (ahalf * 512 + idx);
                float4 va = v4[vbase], vb = v4[vbase + 1];
                float2 f0 = __half22float2(*(__half2*)&kk.x);
                float2 f1 = __half22float2(*(__half2*)&kk.y);
                float2 f2 = __half22float2(*(__half2*)&kk.z);
                float2 f3 = __half22float2(*(__half2*)&kk.w);
                d += f0.x * va.x + f0.y * va.y + f1.x * va.z + f1.y * va.w +
                     f2.x * vb.x + f2.y * vb.y + f3.x * vb.z + f3.y * vb.w;
            }
#pragma unroll
            for (int off = 16; off; off >>= 1) d += __shfl_xor_sync(0xffffffffu, d, off);
            if (lane == 0) sdot[arow * 2 + ahalf] = d;
        }
        __syncthreads();
        if (tid < GR) {
            float u = INVN / (sdot[tid * 2] + sdot[tid * 2 + 1]);
            su[tid] = u;
            g_u[row0 + g * GR + tid] = u;
        }
        __syncthreads();

        // ---- Phase B: column partials, thread-owned columns, reg accum
#pragma unroll
        for (int r = 0; r < GR; r++) {
            float u = su[r];
#pragma unroll
            for (int j = 0; j < 4; j++) {
                uint4 kk = KU[r * 1024 + tid + 256 * j];
                float2 f0 = __half22float2(*(__half2*)&kk.x);
                float2 f1 = __half22float2(*(__half2*)&kk.y);
                float2 f2 = __half22float2(*(__half2*)&kk.z);
                float2 f3 = __half22float2(*(__half2*)&kk.w);
                acc[j][0] += f0.x * u; acc[j][1] += f0.y * u;
                acc[j][2] += f1.x * u; acc[j][3] += f1.y * u;
                acc[j][4] += f2.x * u; acc[j][5] += f2.y * u;
                acc[j][6] += f3.x * u; acc[j][7] += f3.y * u;
            }
        }
        __syncthreads();   // all readers done with buffer b before it is refilled
    }

    // Write column partials (thread t owns cols 8*(t+256j) .. +8)
#pragma unroll
    for (int j = 0; j < 4; j++) {
        float4* out = (float4*)(g_cpart[blk] + (size_t)(tid + 256 * j) * 8);
        out[0] = make_float4(acc[j][0], acc[j][1], acc[j][2], acc[j][3]);
        out[1] = make_float4(acc[j][4], acc[j][5], acc[j][6], acc[j][7]);
    }
}

// v_j = b / sum_chunk cpart[chunk][j]
__global__ void vred_kernel() {
    int j = blockIdx.x * blockDim.x + threadIdx.x;
    float s = 0.0f;
#pragma unroll 8
    for (int ch = 0; ch < FB; ch++) s += g_cpart[ch][j];
    g_v[j] = INVN / s;
}

// ---------------------------------------------------------------------------
// result = sum_ij C_ij * plan_ij ; C recovered as (lnALPHA - ln K16)*reg*cmax
// ---------------------------------------------------------------------------
__global__ void __launch_bounds__(256) final_kernel() {
    const int per_block = (NN / 8) * NN / FINAL_BLOCKS;
    int base = blockIdx.x * per_block;
    float sigma = REG_E * __uint_as_float(g_cmax_bits);
    const uint4* K8 = (const uint4*)g_K16;
    const float4* v4 = (const float4*)g_v;
    float acc = 0.0f;
    for (int t = threadIdx.x; t < per_block; t += 256) {
        int e8 = base + t;
        int row = e8 >> 10;
        int c8 = e8 & 1023;
        uint4 kk = K8[e8];
        float4 va = v4[2 * c8], vb = v4[2 * c8 + 1];
        float u = g_u[row];
        float2 f0 = __half22float2(*(__half2*)&kk.x);
        float2 f1 = __half22float2(*(__half2*)&kk.y);
        float2 f2 = __half22float2(*(__half2*)&kk.z);
        float2 f3 = __half22float2(*(__half2*)&kk.w);
        float s = 0.0f;
        s += f0.x * va.x * (LN_ALPHA - __logf(f0.x));
        s += f0.y * va.y * (LN_ALPHA - __logf(f0.y));
        s += f1.x * va.z * (LN_ALPHA - __logf(f1.x));
        s += f1.y * va.w * (LN_ALPHA - __logf(f1.y));
        s += f2.x * vb.x * (LN_ALPHA - __logf(f2.x));
        s += f2.y * vb.y * (LN_ALPHA - __logf(f2.y));
        s += f3.x * vb.z * (LN_ALPHA - __logf(f3.x));
        s += f3.y * vb.w * (LN_ALPHA - __logf(f3.y));
        acc += u * s;
    }
    acc *= sigma;
    __shared__ float red[256];
    red[threadIdx.x] = acc;
    __syncthreads();
    for (int s = 128; s > 0; s >>= 1) {
        if (threadIdx.x < s) red[threadIdx.x] += red[threadIdx.x + s];
        __syncthreads();
    }
    if (threadIdx.x == 0) g_partial[blockIdx.x] = red[0];
}

__global__ void final_reduce_kernel(float* __restrict__ out) {
    __shared__ float red[256];
    float s = 0.0f;
    for (int i = threadIdx.x; i < FINAL_BLOCKS; i += 256) s += g_partial[i];
    red[threadIdx.x] = s;
    __syncthreads();
    for (int st = 128; st > 0; st >>= 1) {
        if (threadIdx.x < st) red[threadIdx.x] += red[threadIdx.x + st];
        __syncthreads();
    }
    if (threadIdx.x == 0) out[0] = red[0];
}

// ---------------------------------------------------------------------------
extern "C" void kernel_launch(void* const* d_in, const int* in_sizes, int n_in,
                              void* d_out, int out_size) {
    const float* XP = (const float*)d_in[0];
    const float* XQ = (const float*)d_in[1];
    float* out = (float*)d_out;

    // Idempotent, deterministic attribute set (not an allocation, not a stream op)
    cudaFuncSetAttribute(fused_kernel,
                         cudaFuncAttributeMaxDynamicSharedMemorySize, FUSED_SMEM);

    init_kernel<<<NN / 256, 256>>>();
    norms_kernel<<<dim3(NN / 256, 2), 256>>>(XP, XQ);
    gemm_kernel<<<dim3(NN / 128, NN / 128), 256>>>(XP, XQ);
    exp_kernel<<<8192, 256>>>();

    for (int it = 0; it < NITER; it++) {
        fused_kernel<<<FB, 256, FUSED_SMEM>>>();
        vred_kernel<<<NN / 256, 256>>>();
    }

    final_kernel<<<FINAL_BLOCKS, 256>>>();
    final_reduce_kernel<<<1, 256>>>(out);
}

// round 12
// speedup vs baseline: 2.3026x; 1.2115x over previous
#include <cuda_runtime.h>
#include <cuda_fp16.h>

// Problem constants (fixed by reference setup_inputs)
#define NN 8192
#define DD 64
#define NITER 20
#define REG_E 0.05f
#define INVN (1.0f / 8192.0f)
#define ALPHA 32768.0f                 // fp16 scale for K; cancels exactly
#define LN_ALPHA 10.397207708399179f   // ln(2^15)

#define FB 128                // persistent CTAs (1 per SM, co-resident)
#define FROWS (NN / FB)       // 64 rows per CTA
#define GR 4                  // rows per group
#define NG (FROWS / GR)       // 16 groups
#define GBYTES (GR * NN * 2)  // 65536 B per group tile
#define NBUF 3
#define PASSES (NITER + 1)    // 20 sinkhorn iters + 1 final-contraction pass
#define TOTSTEPS (PASSES * NG)   // 336

// Dynamic SMEM layout
#define OFF_VH   (NBUF * GBYTES)     // 196608 : fp16 v cache (16384 B)
#define OFF_TAIL (OFF_VH + 16384)    // 212992 : sdot/su/sred/mbar
#define FUSED_SMEM (OFF_TAIL + 4096) // 217088  (< 227 KB limit)

// Scratch: __device__ globals (no allocation allowed)
__device__ __half g_K16[(size_t)NN * NN];   // 128 MB: C16 then K16 in-place
__device__ float g_x2[NN];
__device__ float g_y2[NN];
__device__ float g_u[NN];                   // u/ALPHA (scale cancels)
__device__ float g_v[NN];
__device__ __half g_vh[NN];
__device__ unsigned g_cmax_bits;
__device__ float g_cpart[FB][NN];           // 4 MB column partial sums
__device__ float g_partial[FB];
__device__ unsigned g_bcount;
__device__ unsigned g_bgen;

// ---------------------------------------------------------------------------
__global__ void init_kernel() {
    int j = blockIdx.x * blockDim.x + threadIdx.x;
    if (j < NN) { g_v[j] = 1.0f; g_vh[j] = __float2half(1.0f); }
    if (j == 0) { g_cmax_bits = 0u; g_bcount = 0u; }
}

// ---------------------------------------------------------------------------
__global__ void norms_kernel(const float* __restrict__ XP,
                             const float* __restrict__ XQ) {
    int row = blockIdx.x * blockDim.x + threadIdx.x;
    if (row >= NN) return;
    const float* X = blockIdx.y ? XQ : XP;
    float* out = blockIdx.y ? g_y2 : g_x2;
    const float4* p = (const float4*)(X + (size_t)row * DD);
    float s = 0.0f;
#pragma unroll
    for (int i = 0; i < DD / 4; i++) {
        float4 a = p[i];
        s += a.x * a.x + a.y * a.y + a.z * a.z + a.w * a.w;
    }
    out[row] = s;
}

// ---------------------------------------------------------------------------
// Tensor-core GEMM: C = max(x2 + y2 - 2*XP@XQ^T, 0) stored as fp16.
// ---------------------------------------------------------------------------
#define SROW 72
__global__ void __launch_bounds__(256) gemm_kernel(const float* __restrict__ XP,
                                                   const float* __restrict__ XQ) {
    __shared__ __half As[128 * SROW];
    __shared__ __half Bs[128 * SROW];
    __shared__ float red[256];

    const int tid = threadIdx.x;
    const int warp = tid >> 5, lane = tid & 31;
    const int wm = warp >> 2, wn = warp & 3;
    const int g = lane >> 2, t = lane & 3;
    const int bm = blockIdx.y, bn = blockIdx.x;

#pragma unroll
    for (int i = 0; i < 8; i++) {
        int idx = i * 256 + tid;
        int r = idx >> 4;
        int c4 = idx & 15;
        float4 a = *(const float4*)(XP + (size_t)(bm * 128 + r) * DD + c4 * 4);
        __half2 a01 = __floats2half2_rn(a.x, a.y);
        __half2 a23 = __floats2half2_rn(a.z, a.w);
        uint2 pa; pa.x = *(unsigned*)&a01; pa.y = *(unsigned*)&a23;
        *(uint2*)(As + r * SROW + c4 * 4) = pa;
        float4 b = *(const float4*)(XQ + (size_t)(bn * 128 + r) * DD + c4 * 4);
        __half2 b01 = __floats2half2_rn(b.x, b.y);
        __half2 b23 = __floats2half2_rn(b.z, b.w);
        uint2 pb; pb.x = *(unsigned*)&b01; pb.y = *(unsigned*)&b23;
        *(uint2*)(Bs + r * SROW + c4 * 4) = pb;
    }
    __syncthreads();

    float acc[4][4][4];
#pragma unroll
    for (int mt = 0; mt < 4; mt++)
#pragma unroll
        for (int nt = 0; nt < 4; nt++)
#pragma unroll
            for (int r = 0; r < 4; r++) acc[mt][nt][r] = 0.0f;

#pragma unroll
    for (int ks = 0; ks < 4; ks++) {
        const int k0 = ks * 16;
        unsigned af[4][4], bf[4][2];
#pragma unroll
        for (int mt = 0; mt < 4; mt++) {
            int row = wm * 64 + mt * 16;
            af[mt][0] = *(unsigned*)(As + (row + g) * SROW + k0 + 2 * t);
            af[mt][1] = *(unsigned*)(As + (row + g + 8) * SROW + k0 + 2 * t);
            af[mt][2] = *(unsigned*)(As + (row + g) * SROW + k0 + 2 * t + 8);
            af[mt][3] = *(unsigned*)(As + (row + g + 8) * SROW + k0 + 2 * t + 8);
        }
#pragma unroll
        for (int nt = 0; nt < 4; nt++) {
            int col = wn * 32 + nt * 8 + g;
            bf[nt][0] = *(unsigned*)(Bs + col * SROW + k0 + 2 * t);
            bf[nt][1] = *(unsigned*)(Bs + col * SROW + k0 + 2 * t + 8);
        }
#pragma unroll
        for (int mt = 0; mt < 4; mt++)
#pragma unroll
            for (int nt = 0; nt < 4; nt++) {
                asm volatile(
                    "mma.sync.aligned.m16n8k16.row.col.f32.f16.f16.f32 "
                    "{%0,%1,%2,%3},{%4,%5,%6,%7},{%8,%9},{%0,%1,%2,%3};\n"
                    : "+f"(acc[mt][nt][0]), "+f"(acc[mt][nt][1]),
                      "+f"(acc[mt][nt][2]), "+f"(acc[mt][nt][3])
                    : "r"(af[mt][0]), "r"(af[mt][1]), "r"(af[mt][2]), "r"(af[mt][3]),
                      "r"(bf[nt][0]), "r"(bf[nt][1]));
            }
    }

    float lmax = 0.0f;
#pragma unroll
    for (int mt = 0; mt < 4; mt++) {
        int r0 = bm * 128 + wm * 64 + mt * 16 + g;
        float xA = g_x2[r0], xB = g_x2[r0 + 8];
#pragma unroll
        for (int nt = 0; nt < 4; nt++) {
            int c0 = bn * 128 + wn * 32 + nt * 8 + 2 * t;
            float y0 = g_y2[c0], y1 = g_y2[c0 + 1];
            float v00 = fmaxf(xA + y0 - 2.0f * acc[mt][nt][0], 0.0f);
            float v01 = fmaxf(xA + y1 - 2.0f * acc[mt][nt][1], 0.0f);
            float v10 = fmaxf(xB + y0 - 2.0f * acc[mt][nt][2], 0.0f);
            float v11 = fmaxf(xB + y1 - 2.0f * acc[mt][nt][3], 0.0f);
            lmax = fmaxf(lmax, fmaxf(fmaxf(v00, v01), fmaxf(v10, v11)));
            *(__half2*)(g_K16 + (size_t)r0 * NN + c0) = __floats2half2_rn(v00, v01);
            *(__half2*)(g_K16 + (size_t)(r0 + 8) * NN + c0) = __floats2half2_rn(v10, v11);
        }
    }

    red[tid] = lmax;
    __syncthreads();
    for (int s = 128; s > 0; s >>= 1) {
        if (tid < s) red[tid] = fmaxf(red[tid], red[tid + s]);
        __syncthreads();
    }
    if (tid == 0) atomicMax(&g_cmax_bits, __float_as_uint(red[0]));
}

// ---------------------------------------------------------------------------
// In-place: K16 = ALPHA * exp(-C16 / (reg * Cmax))
// ---------------------------------------------------------------------------
__global__ void exp_kernel() {
    float cmax = __uint_as_float(g_cmax_bits);
    float s = -1.0f / (REG_E * cmax);
    uint4* K8 = (uint4*)g_K16;
    int total8 = NN * (NN / 8);
    int stride = gridDim.x * blockDim.x;
    for (int i = blockIdx.x * blockDim.x + threadIdx.x; i < total8; i += stride) {
        uint4 c = K8[i];
        float2 c0 = __half22float2(*(__half2*)&c.x);
        float2 c1 = __half22float2(*(__half2*)&c.y);
        float2 c2 = __half22float2(*(__half2*)&c.z);
        float2 c3 = __half22float2(*(__half2*)&c.w);
        __half2 h0 = __floats2half2_rn(__expf(c0.x * s) * ALPHA, __expf(c0.y * s) * ALPHA);
        __half2 h1 = __floats2half2_rn(__expf(c1.x * s) * ALPHA, __expf(c1.y * s) * ALPHA);
        __half2 h2 = __floats2half2_rn(__expf(c2.x * s) * ALPHA, __expf(c2.y * s) * ALPHA);
        __half2 h3 = __floats2half2_rn(__expf(c3.x * s) * ALPHA, __expf(c3.y * s) * ALPHA);
        uint4 o;
        o.x = *(unsigned*)&h0; o.y = *(unsigned*)&h1;
        o.z = *(unsigned*)&h2; o.w = *(unsigned*)&h3;
        K8[i] = o;
    }
}

// ---------------------------------------------------------------------------
// Grid-wide sense-reversal barrier. Safe: grid=128 CTAs, 1 CTA/SM (smem),
// 148 SMs -> all co-resident.
// ---------------------------------------------------------------------------
__device__ __forceinline__ void grid_bar() {
    __syncthreads();
    if (threadIdx.x == 0) {
        __threadfence();
        unsigned gen = *((volatile unsigned*)&g_bgen);
        if (atomicAdd(&g_bcount, 1u) == FB - 1) {
            g_bcount = 0;
            __threadfence();
            atomicAdd(&g_bgen, 1u);
        } else {
            while (*((volatile unsigned*)&g_bgen) == gen) {}
        }
        __threadfence();
    }
    __syncthreads();
}

__device__ __forceinline__ void mwait(unsigned mb, int ph) {
    unsigned done = 0;
    while (!done) {
        asm volatile(
            "{\n\t.reg .pred p;\n\t"
            "mbarrier.try_wait.parity.acquire.cta.shared::cta.b64 p, [%1], %2, 0x989680;\n\t"
            "selp.b32 %0, 1, 0, p;\n\t}"
            : "=r"(done) : "r"(mb), "r"(ph) : "memory");
    }
}

__device__ __forceinline__ void issue_tile(int step, int row_base,
                                           const unsigned* buf_s,
                                           const unsigned* mbar_s) {
    if (threadIdx.x == 0 && step < TOTSTEPS) {
        int g = step & (NG - 1);              // rows depend only on g (K constant)
        int b = step % NBUF;
        unsigned long long gsrc;
        const __half* src = g_K16 + (size_t)(row_base + g * GR) * NN;
        asm volatile("cvta.to.global.u64 %0, %1;" : "=l"(gsrc) : "l"(src));
        asm volatile("mbarrier.arrive.expect_tx.shared.b64 _, [%0], %1;"
                     :: "r"(mbar_s[b]), "r"((unsigned)GBYTES) : "memory");
        asm volatile("cp.async.bulk.shared::cta.global.mbarrier::complete_tx::bytes "
                     "[%0], [%1], %2, [%3];"
                     :: "r"(buf_s[b]), "l"(gsrc), "r"((unsigned)GBYTES), "r"(mbar_s[b])
                     : "memory");
    }
}

// ---------------------------------------------------------------------------
// Persistent Sinkhorn: 20 iterations + final contraction, ONE kernel.
// Per iteration (per CTA, 64 rows, depth-3 TMA pipeline that never drains):
//   groups of 4 rows: phase A (u = INVN/dot(K,v), 4 warps/row, v fp16 in smem)
//                     phase B (col partials += K*u, thread-owned cols, regs)
//   -> cpart write -> grid_bar -> cooperative v-reduce (64 cols/CTA)
//   -> grid_bar -> next iteration.
// Pass 21: final contraction sum C.*plan via ln recovery, same pipeline.
// ---------------------------------------------------------------------------
__global__ void __launch_bounds__(512, 1) sink_kernel(float* __restrict__ out) {
    extern __shared__ __align__(128) unsigned char s_raw[];
    const int tid = threadIdx.x;
    const int blk = blockIdx.x;
    const int row_base = blk * FROWS;

    const uint4* bufs4[NBUF];
    unsigned buf_s[NBUF], mbar_s[NBUF];
    float* tail = (float*)(s_raw + OFF_TAIL);
    float* sdot = tail;             // [GR][4]  = 16 floats
    float* su = tail + 16;          // [GR]
    float* sred = tail + 32;        // [8][64] = 512 floats
    unsigned long long* mbar = (unsigned long long*)(tail + 32 + 512);
    const uint4* vh4 = (const uint4*)(s_raw + OFF_VH);     // 1024 uint4
    uint4* vh4w = (uint4*)(s_raw + OFF_VH);

#pragma unroll
    for (int b = 0; b < NBUF; b++) {
        bufs4[b] = (const uint4*)(s_raw + b * GBYTES);
        buf_s[b] = (unsigned)__cvta_generic_to_shared(s_raw + b * GBYTES);
        mbar_s[b] = (unsigned)__cvta_generic_to_shared(&mbar[b]);
    }
    if (tid == 0) {
#pragma unroll
        for (int b = 0; b < NBUF; b++)
            asm volatile("mbarrier.init.shared.b64 [%0], 1;" :: "r"(mbar_s[b]) : "memory");
    }
    __syncthreads();

    // Prologue: fill the pipeline
    issue_tile(0, row_base, buf_s, mbar_s);
    issue_tile(1, row_base, buf_s, mbar_s);
    issue_tile(2, row_base, buf_s, mbar_s);

    int ph[NBUF] = {0, 0, 0};
    const int warp = tid >> 5, lane = tid & 31;
    const int arow = warp >> 2, aq = warp & 3;   // 4 warps per row

    float acc[16];
#pragma unroll
    for (int k = 0; k < 16; k++) acc[k] = 0.0f;

    int G = 0;
    const uint4* gvh4 = (const uint4*)g_vh;

    for (int p = 0; p < NITER; p++) {
        // load fp16 v into smem (16 KB)
        vh4w[tid] = gvh4[tid];
        vh4w[tid + 512] = gvh4[tid + 512];
        __syncthreads();

        for (int g = 0; g < NG; g++, G++) {
            const int b = G % NBUF;
            mwait(mbar_s[b], ph[b]); ph[b] ^= 1;
            const uint4* KU = bufs4[b];

            // ---- Phase A: row dots, 4 warps/row, quarter-rows of 256 uint4
            {
                const uint4* rowp = KU + arow * 1024 + aq * 256;
                const uint4* vp = vh4 + aq * 256;
                float d = 0.0f;
#pragma unroll
                for (int k = 0; k < 8; k++) {
                    int idx = lane + 32 * k;
                    uint4 kk = rowp[idx];
                    uint4 vv = vp[idx];
                    float2 k0 = __half22float2(*(__half2*)&kk.x);
                    float2 k1 = __half22float2(*(__half2*)&kk.y);
                    float2 k2 = __half22float2(*(__half2*)&kk.z);
                    float2 k3 = __half22float2(*(__half2*)&kk.w);
                    float2 v0 = __half22float2(*(__half2*)&vv.x);
                    float2 v1 = __half22float2(*(__half2*)&vv.y);
                    float2 v2 = __half22float2(*(__half2*)&vv.z);
                    float2 v3 = __half22float2(*(__half2*)&vv.w);
                    d += k0.x * v0.x + k0.y * v0.y + k1.x * v1.x + k1.y * v1.y +
                         k2.x * v2.x + k2.y * v2.y + k3.x * v3.x + k3.y * v3.y;
                }
#pragma unroll
                for (int off = 16; off; off >>= 1) d += __shfl_xor_sync(0xffffffffu, d, off);
                if (lane == 0) sdot[arow * 4 + aq] = d;
            }
            __syncthreads();
            if (tid < GR) {
                float u = INVN / (sdot[tid * 4] + sdot[tid * 4 + 1] +
                                  sdot[tid * 4 + 2] + sdot[tid * 4 + 3]);
                su[tid] = u;
                g_u[row_base + g * GR + tid] = u;
            }
            __syncthreads();

            // ---- Phase B: column partials (thread owns cols 16*tid..+16)
#pragma unroll
            for (int r = 0; r < GR; r++) {
                float u = su[r];
#pragma unroll
                for (int j = 0; j < 2; j++) {
                    uint4 kk = KU[r * 1024 + tid * 2 + j];
                    float2 f0 = __half22float2(*(__half2*)&kk.x);
                    float2 f1 = __half22float2(*(__half2*)&kk.y);
                    float2 f2 = __half22float2(*(__half2*)&kk.z);
                    float2 f3 = __half22float2(*(__half2*)&kk.w);
                    acc[j * 8 + 0] += f0.x * u; acc[j * 8 + 1] += f0.y * u;
                    acc[j * 8 + 2] += f1.x * u; acc[j * 8 + 3] += f1.y * u;
                    acc[j * 8 + 4] += f2.x * u; acc[j * 8 + 5] += f2.y * u;
                    acc[j * 8 + 6] += f3.x * u; acc[j * 8 + 7] += f3.y * u;
                }
            }
            __syncthreads();          // all readers done -> buffer reusable
            issue_tile(G + NBUF, row_base, buf_s, mbar_s);
        }

        // write column partials, reset accumulators
        {
            float4* outp = (float4*)(g_cpart[blk] + tid * 16);
            outp[0] = make_float4(acc[0], acc[1], acc[2], acc[3]);
            outp[1] = make_float4(acc[4], acc[5], acc[6], acc[7]);
            outp[2] = make_float4(acc[8], acc[9], acc[10], acc[11]);
            outp[3] = make_float4(acc[12], acc[13], acc[14], acc[15]);
#pragma unroll
            for (int k = 0; k < 16; k++) acc[k] = 0.0f;
        }
        grid_bar();

        // cooperative v-reduce: CTA owns 64 columns
        {
            int c0 = blk * 64;
            int col = tid & 63;
            int part = tid >> 6;       // 0..7, 16 chunks each
            float s = 0.0f;
#pragma unroll
            for (int k = 0; k < 16; k++) s += g_cpart[part * 16 + k][c0 + col];
            sred[part * 64 + col] = s;
            __syncthreads();
            if (tid < 64) {
                float t = 0.0f;
#pragma unroll
                for (int q = 0; q < 8; q++) t += sred[q * 64 + tid];
                float v = INVN / t;
                g_v[c0 + tid] = v;
                g_vh[c0 + tid] = __float2half(v);
            }
        }
        grid_bar();
    }

    // -------- final pass: sum C .* plan, C = (lnALPHA - lnK)*reg*cmax --------
    float sigma = REG_E * __uint_as_float(g_cmax_bits);
    const float4* v4 = (const float4*)g_v;
    float facc = 0.0f;
    for (int g = 0; g < NG; g++, G++) {
        const int b = G % NBUF;
        mwait(mbar_s[b], ph[b]); ph[b] ^= 1;
        const uint4* KU = bufs4[b];
#pragma unroll
        for (int r = 0; r < GR; r++) {
            float u = __ldg(&g_u[row_base + g * GR + r]);
            float rs = 0.0f;
#pragma unroll
            for (int j = 0; j < 2; j++) {
                uint4 kk = KU[r * 1024 + tid * 2 + j];
                float4 va = v4[(tid * 2 + j) * 2];
                float4 vb = v4[(tid * 2 + j) * 2 + 1];
                float2 f0 = __half22float2(*(__half2*)&kk.x);
                float2 f1 = __half22float2(*(__half2*)&kk.y);
                float2 f2 = __half22float2(*(__half2*)&kk.z);
                float2 f3 = __half22float2(*(__half2*)&kk.w);
                rs += f0.x * va.x * (LN_ALPHA - __logf(f0.x));
                rs += f0.y * va.y * (LN_ALPHA - __logf(f0.y));
                rs += f1.x * va.z * (LN_ALPHA - __logf(f1.x));
                rs += f1.y * va.w * (LN_ALPHA - __logf(f1.y));
                rs += f2.x * vb.x * (LN_ALPHA - __logf(f2.x));
                rs += f2.y * vb.y * (LN_ALPHA - __logf(f2.y));
                rs += f3.x * vb.z * (LN_ALPHA - __logf(f3.x));
                rs += f3.y * vb.w * (LN_ALPHA - __logf(f3.y));
            }
            facc += u * rs;
        }
        __syncthreads();
        issue_tile(G + NBUF, row_base, buf_s, mbar_s);   // no-op past end
    }
    facc *= sigma;

    // block reduce -> g_partial[blk]
    sred[tid >= 512 ? 0 : 0] = 0.0f;  // no-op keep compiler happy
    {
        __syncthreads();
        float* fr = sred;             // reuse 512-float region
        fr[tid] = facc;
        __syncthreads();
        for (int s = 256; s > 0; s >>= 1) {
            if (tid < s) fr[tid] += fr[tid + s];
            __syncthreads();
        }
        if (tid == 0) g_partial[blk] = fr[0];
    }
    grid_bar();

    if (blk == 0) {
        float s = (tid < FB) ? g_partial[tid] : 0.0f;
        sred[tid] = s;
        __syncthreads();
        for (int st = 256; st > 0; st >>= 1) {
            if (tid < st) sred[tid] += sred[tid + st];
            __syncthreads();
        }
        if (tid == 0) out[0] = sred[0];
    }
}

// ---------------------------------------------------------------------------
extern "C" void kernel_launch(void* const* d_in, const int* in_sizes, int n_in,
                              void* d_out, int out_size) {
    const float* XP = (const float*)d_in[0];
    const float* XQ = (const float*)d_in[1];
    float* out = (float*)d_out;

    cudaFuncSetAttribute(sink_kernel,
                         cudaFuncAttributeMaxDynamicSharedMemorySize, FUSED_SMEM);

    init_kernel<<<NN / 256, 256>>>();
    norms_kernel<<<dim3(NN / 256, 2), 256>>>(XP, XQ);
    gemm_kernel<<<dim3(NN / 128, NN / 128), 256>>>(XP, XQ);
    exp_kernel<<<8192, 256>>>();
    sink_kernel<<<FB, 512, FUSED_SMEM>>>(out);
}

// round 13
// speedup vs baseline: 2.5328x; 1.1000x over previous
#include <cuda_runtime.h>
#include <cuda_fp16.h>

// Problem constants (fixed by reference setup_inputs)
#define NN 8192
#define DD 64
#define NITER 20
#define REG_E 0.05f
#define INVN (1.0f / 8192.0f)
#define ALPHA 32768.0f                 // fp16 scale for K; cancels exactly
#define LN_ALPHA 10.397207708399179f   // ln(2^15)

#define FB 128                // persistent CTAs (1 per SM, co-resident)
#define FROWS (NN / FB)       // 64 rows per CTA
#define GR 4                  // rows per group
#define NG (FROWS / GR)       // 16 groups
#define GBYTES (GR * NN * 2)  // 65536 B per group tile
#define NBUF 3
#define PASSES (NITER + 1)    // 20 sinkhorn iters + 1 final-contraction pass
#define TOTSTEPS (PASSES * NG)   // 336

// Dynamic SMEM: 3 tile buffers + small tail
#define OFF_TAIL (NBUF * GBYTES)      // 196608
#define FUSED_SMEM (OFF_TAIL + 4096)  // 200704 (< 227 KB limit)

// Scratch: __device__ globals (no allocation allowed)
__device__ __half g_K16[(size_t)NN * NN];   // 128 MB: C16 then K16 in-place
__device__ float g_x2[NN];
__device__ float g_y2[NN];
__device__ float g_u[NN];                   // u/ALPHA (scale cancels)
__device__ float g_v[NN];
__device__ unsigned g_cmax_bits;
__device__ float g_cpart[FB][NN];           // 4 MB column partial sums
__device__ float g_partial[FB];
__device__ unsigned g_bcount;
__device__ unsigned g_bgen;

// ---------------------------------------------------------------------------
__global__ void init_kernel() {
    int j = blockIdx.x * blockDim.x + threadIdx.x;
    if (j < NN) g_v[j] = 1.0f;
    if (j == 0) { g_cmax_bits = 0u; g_bcount = 0u; }
}

// ---------------------------------------------------------------------------
__global__ void norms_kernel(const float* __restrict__ XP,
                             const float* __restrict__ XQ) {
    int row = blockIdx.x * blockDim.x + threadIdx.x;
    if (row >= NN) return;
    const float* X = blockIdx.y ? XQ : XP;
    float* out = blockIdx.y ? g_y2 : g_x2;
    const float4* p = (const float4*)(X + (size_t)row * DD);
    float s = 0.0f;
#pragma unroll
    for (int i = 0; i < DD / 4; i++) {
        float4 a = p[i];
        s += a.x * a.x + a.y * a.y + a.z * a.z + a.w * a.w;
    }
    out[row] = s;
}

// ---------------------------------------------------------------------------
// Tensor-core GEMM: C = max(x2 + y2 - 2*XP@XQ^T, 0) stored as fp16.
// ---------------------------------------------------------------------------
#define SROW 72
__global__ void __launch_bounds__(256) gemm_kernel(const float* __restrict__ XP,
                                                   const float* __restrict__ XQ) {
    __shared__ __half As[128 * SROW];
    __shared__ __half Bs[128 * SROW];
    __shared__ float red[256];

    const int tid = threadIdx.x;
    const int warp = tid >> 5, lane = tid & 31;
    const int wm = warp >> 2, wn = warp & 3;
    const int g = lane >> 2, t = lane & 3;
    const int bm = blockIdx.y, bn = blockIdx.x;

#pragma unroll
    for (int i = 0; i < 8; i++) {
        int idx = i * 256 + tid;
        int r = idx >> 4;
        int c4 = idx & 15;
        float4 a = *(const float4*)(XP + (size_t)(bm * 128 + r) * DD + c4 * 4);
        __half2 a01 = __floats2half2_rn(a.x, a.y);
        __half2 a23 = __floats2half2_rn(a.z, a.w);
        uint2 pa; pa.x = *(unsigned*)&a01; pa.y = *(unsigned*)&a23;
        *(uint2*)(As + r * SROW + c4 * 4) = pa;
        float4 b = *(const float4*)(XQ + (size_t)(bn * 128 + r) * DD + c4 * 4);
        __half2 b01 = __floats2half2_rn(b.x, b.y);
        __half2 b23 = __floats2half2_rn(b.z, b.w);
        uint2 pb; pb.x = *(unsigned*)&b01; pb.y = *(unsigned*)&b23;
        *(uint2*)(Bs + r * SROW + c4 * 4) = pb;
    }
    __syncthreads();

    float acc[4][4][4];
#pragma unroll
    for (int mt = 0; mt < 4; mt++)
#pragma unroll
        for (int nt = 0; nt < 4; nt++)
#pragma unroll
            for (int r = 0; r < 4; r++) acc[mt][nt][r] = 0.0f;

#pragma unroll
    for (int ks = 0; ks < 4; ks++) {
        const int k0 = ks * 16;
        unsigned af[4][4], bf[4][2];
#pragma unroll
        for (int mt = 0; mt < 4; mt++) {
            int row = wm * 64 + mt * 16;
            af[mt][0] = *(unsigned*)(As + (row + g) * SROW + k0 + 2 * t);
            af[mt][1] = *(unsigned*)(As + (row + g + 8) * SROW + k0 + 2 * t);
            af[mt][2] = *(unsigned*)(As + (row + g) * SROW + k0 + 2 * t + 8);
            af[mt][3] = *(unsigned*)(As + (row + g + 8) * SROW + k0 + 2 * t + 8);
        }
#pragma unroll
        for (int nt = 0; nt < 4; nt++) {
            int col = wn * 32 + nt * 8 + g;
            bf[nt][0] = *(unsigned*)(Bs + col * SROW + k0 + 2 * t);
            bf[nt][1] = *(unsigned*)(Bs + col * SROW + k0 + 2 * t + 8);
        }
#pragma unroll
        for (int mt = 0; mt < 4; mt++)
#pragma unroll
            for (int nt = 0; nt < 4; nt++) {
                asm volatile(
                    "mma.sync.aligned.m16n8k16.row.col.f32.f16.f16.f32 "
                    "{%0,%1,%2,%3},{%4,%5,%6,%7},{%8,%9},{%0,%1,%2,%3};\n"
                    : "+f"(acc[mt][nt][0]), "+f"(acc[mt][nt][1]),
                      "+f"(acc[mt][nt][2]), "+f"(acc[mt][nt][3])
                    : "r"(af[mt][0]), "r"(af[mt][1]), "r"(af[mt][2]), "r"(af[mt][3]),
                      "r"(bf[nt][0]), "r"(bf[nt][1]));
            }
    }

    float lmax = 0.0f;
#pragma unroll
    for (int mt = 0; mt < 4; mt++) {
        int r0 = bm * 128 + wm * 64 + mt * 16 + g;
        float xA = g_x2[r0], xB = g_x2[r0 + 8];
#pragma unroll
        for (int nt = 0; nt < 4; nt++) {
            int c0 = bn * 128 + wn * 32 + nt * 8 + 2 * t;
            float y0 = g_y2[c0], y1 = g_y2[c0 + 1];
            float v00 = fmaxf(xA + y0 - 2.0f * acc[mt][nt][0], 0.0f);
            float v01 = fmaxf(xA + y1 - 2.0f * acc[mt][nt][1], 0.0f);
            float v10 = fmaxf(xB + y0 - 2.0f * acc[mt][nt][2], 0.0f);
            float v11 = fmaxf(xB + y1 - 2.0f * acc[mt][nt][3], 0.0f);
            lmax = fmaxf(lmax, fmaxf(fmaxf(v00, v01), fmaxf(v10, v11)));
            *(__half2*)(g_K16 + (size_t)r0 * NN + c0) = __floats2half2_rn(v00, v01);
            *(__half2*)(g_K16 + (size_t)(r0 + 8) * NN + c0) = __floats2half2_rn(v10, v11);
        }
    }

    red[tid] = lmax;
    __syncthreads();
    for (int s = 128; s > 0; s >>= 1) {
        if (tid < s) red[tid] = fmaxf(red[tid], red[tid + s]);
        __syncthreads();
    }
    if (tid == 0) atomicMax(&g_cmax_bits, __float_as_uint(red[0]));
}

// ---------------------------------------------------------------------------
// In-place: K16 = ALPHA * exp(-C16 / (reg * Cmax))
// ---------------------------------------------------------------------------
__global__ void exp_kernel() {
    float cmax = __uint_as_float(g_cmax_bits);
    float s = -1.0f / (REG_E * cmax);
    uint4* K8 = (uint4*)g_K16;
    int total8 = NN * (NN / 8);
    int stride = gridDim.x * blockDim.x;
    for (int i = blockIdx.x * blockDim.x + threadIdx.x; i < total8; i += stride) {
        uint4 c = K8[i];
        float2 c0 = __half22float2(*(__half2*)&c.x);
        float2 c1 = __half22float2(*(__half2*)&c.y);
        float2 c2 = __half22float2(*(__half2*)&c.z);
        float2 c3 = __half22float2(*(__half2*)&c.w);
        __half2 h0 = __floats2half2_rn(__expf(c0.x * s) * ALPHA, __expf(c0.y * s) * ALPHA);
        __half2 h1 = __floats2half2_rn(__expf(c1.x * s) * ALPHA, __expf(c1.y * s) * ALPHA);
        __half2 h2 = __floats2half2_rn(__expf(c2.x * s) * ALPHA, __expf(c2.y * s) * ALPHA);
        __half2 h3 = __floats2half2_rn(__expf(c3.x * s) * ALPHA, __expf(c3.y * s) * ALPHA);
        uint4 o;
        o.x = *(unsigned*)&h0; o.y = *(unsigned*)&h1;
        o.z = *(unsigned*)&h2; o.w = *(unsigned*)&h3;
        K8[i] = o;
    }
}

// ---------------------------------------------------------------------------
// Grid-wide sense-reversal barrier (128 CTAs, 1/SM, all co-resident).
// ---------------------------------------------------------------------------
__device__ __forceinline__ void grid_bar() {
    __syncthreads();
    if (threadIdx.x == 0) {
        __threadfence();
        unsigned gen = *((volatile unsigned*)&g_bgen);
        if (atomicAdd(&g_bcount, 1u) == FB - 1) {
            g_bcount = 0;
            __threadfence();
            atomicAdd(&g_bgen, 1u);
        } else {
            while (*((volatile unsigned*)&g_bgen) == gen) {}
        }
        __threadfence();
    }
    __syncthreads();
}

__device__ __forceinline__ void mwait(unsigned mb, int ph) {
    unsigned done = 0;
    while (!done) {
        asm volatile(
            "{\n\t.reg .pred p;\n\t"
            "mbarrier.try_wait.parity.acquire.cta.shared::cta.b64 p, [%1], %2, 0x989680;\n\t"
            "selp.b32 %0, 1, 0, p;\n\t}"
            : "=r"(done) : "r"(mb), "r"(ph) : "memory");
    }
}

__device__ __forceinline__ void issue_tile(int step, int row_base,
                                           const unsigned* buf_s,
                                           const unsigned* mbar_s) {
    if (threadIdx.x == 0 && step < TOTSTEPS) {
        int g = step & (NG - 1);              // rows depend only on g (K constant)
        int b = step % NBUF;
        unsigned long long gsrc;
        const __half* src = g_K16 + (size_t)(row_base + g * GR) * NN;
        asm volatile("cvta.to.global.u64 %0, %1;" : "=l"(gsrc) : "l"(src));
        asm volatile("mbarrier.arrive.expect_tx.shared.b64 _, [%0], %1;"
                     :: "r"(mbar_s[b]), "r"((unsigned)GBYTES) : "memory");
        asm volatile("cp.async.bulk.shared::cta.global.mbarrier::complete_tx::bytes "
                     "[%0], [%1], %2, [%3];"
                     :: "r"(buf_s[b]), "l"(gsrc), "r"((unsigned)GBYTES), "r"(mbar_s[b])
                     : "memory");
    }
}

// ---------------------------------------------------------------------------
// Persistent Sinkhorn: 20 iterations + final contraction, ONE kernel.
// Column-ownership design: thread t owns columns [16t, 16t+16) of all rows.
// Per group: load K tile slice into REGISTERS once (phase A), partial dots
// with register-cached fp32 v, block-reduce -> u; TMA refill issued
// immediately after the loads are done; phase B (cols += K*u) runs from
// registers while the buffer refills. 2 syncthreads/group, K read from SMEM
// exactly once.
// ---------------------------------------------------------------------------
__global__ void __launch_bounds__(512, 1) sink_kernel(float* __restrict__ out) {
    extern __shared__ __align__(128) unsigned char s_raw[];
    const int tid = threadIdx.x;
    const int blk = blockIdx.x;
    const int row_base = blk * FROWS;

    const uint4* bufs4[NBUF];
    unsigned buf_s[NBUF], mbar_s[NBUF];
    float* tail = (float*)(s_raw + OFF_TAIL);
    float* swarp = tail;            // [16 warps][GR] = 64 floats
    float* su = tail + 64;          // [GR]
    float* sred = tail + 80;        // [512] (v-reduce / final reduce)
    unsigned long long* mbar = (unsigned long long*)(tail + 80 + 512);

#pragma unroll
    for (int b = 0; b < NBUF; b++) {
        bufs4[b] = (const uint4*)(s_raw + b * GBYTES);
        buf_s[b] = (unsigned)__cvta_generic_to_shared(s_raw + b * GBYTES);
        mbar_s[b] = (unsigned)__cvta_generic_to_shared(&mbar[b]);
    }
    if (tid == 0) {
#pragma unroll
        for (int b = 0; b < NBUF; b++)
            asm volatile("mbarrier.init.shared.b64 [%0], 1;" :: "r"(mbar_s[b]) : "memory");
    }
    __syncthreads();

    issue_tile(0, row_base, buf_s, mbar_s);
    issue_tile(1, row_base, buf_s, mbar_s);
    issue_tile(2, row_base, buf_s, mbar_s);

    int ph[NBUF] = {0, 0, 0};
    const int warp = tid >> 5, lane = tid & 31;

    float acc[16];
#pragma unroll
    for (int k = 0; k < 16; k++) acc[k] = 0.0f;

    int G = 0;

    for (int p = 0; p < NITER; p++) {
        // register-cache fp32 v for this thread's 16 columns
        float vr[16];
        {
            const float4* vp = (const float4*)(g_v + tid * 16);
#pragma unroll
            for (int q = 0; q < 4; q++) {
                float4 vv = vp[q];
                vr[q * 4 + 0] = vv.x; vr[q * 4 + 1] = vv.y;
                vr[q * 4 + 2] = vv.z; vr[q * 4 + 3] = vv.w;
            }
        }

        for (int g = 0; g < NG; g++, G++) {
            const int b = G % NBUF;
            mwait(mbar_s[b], ph[b]); ph[b] ^= 1;
            const uint4* KU = bufs4[b];

            // ---- Phase A: load K slice into regs + per-thread partial dots
            uint4 kreg[GR][2];
            float d[GR];
#pragma unroll
            for (int r = 0; r < GR; r++) {
                kreg[r][0] = KU[r * 1024 + tid * 2];
                kreg[r][1] = KU[r * 1024 + tid * 2 + 1];
                float s = 0.0f;
#pragma unroll
                for (int j = 0; j < 2; j++) {
                    float2 f0 = __half22float2(*(__half2*)&kreg[r][j].x);
                    float2 f1 = __half22float2(*(__half2*)&kreg[r][j].y);
                    float2 f2 = __half22float2(*(__half2*)&kreg[r][j].z);
                    float2 f3 = __half22float2(*(__half2*)&kreg[r][j].w);
                    s += f0.x * vr[j * 8 + 0] + f0.y * vr[j * 8 + 1] +
                         f1.x * vr[j * 8 + 2] + f1.y * vr[j * 8 + 3] +
                         f2.x * vr[j * 8 + 4] + f2.y * vr[j * 8 + 5] +
                         f3.x * vr[j * 8 + 6] + f3.y * vr[j * 8 + 7];
                }
                d[r] = s;
            }
#pragma unroll
            for (int r = 0; r < GR; r++) {
#pragma unroll
                for (int off = 16; off; off >>= 1)
                    d[r] += __shfl_xor_sync(0xffffffffu, d[r], off);
            }
            if (lane == 0) {
#pragma unroll
                for (int r = 0; r < GR; r++) swarp[warp * GR + r] = d[r];
            }
            __syncthreads();             // buffer b fully consumed (loads done)
            issue_tile(G + NBUF, row_base, buf_s, mbar_s);  // refill overlaps B

            if (tid < GR) {
                float s = 0.0f;
#pragma unroll
                for (int w = 0; w < 16; w++) s += swarp[w * GR + tid];
                float u = INVN / s;
                su[tid] = u;
                g_u[row_base + g * GR + tid] = u;
            }
            __syncthreads();

            // ---- Phase B: column partials from registers
#pragma unroll
            for (int r = 0; r < GR; r++) {
                float u = su[r];
#pragma unroll
                for (int j = 0; j < 2; j++) {
                    float2 f0 = __half22float2(*(__half2*)&kreg[r][j].x);
                    float2 f1 = __half22float2(*(__half2*)&kreg[r][j].y);
                    float2 f2 = __half22float2(*(__half2*)&kreg[r][j].z);
                    float2 f3 = __half22float2(*(__half2*)&kreg[r][j].w);
                    acc[j * 8 + 0] += f0.x * u; acc[j * 8 + 1] += f0.y * u;
                    acc[j * 8 + 2] += f1.x * u; acc[j * 8 + 3] += f1.y * u;
                    acc[j * 8 + 4] += f2.x * u; acc[j * 8 + 5] += f2.y * u;
                    acc[j * 8 + 6] += f3.x * u; acc[j * 8 + 7] += f3.y * u;
                }
            }
        }

        // write column partials, reset accumulators
        {
            float4* outp = (float4*)(g_cpart[blk] + tid * 16);
            outp[0] = make_float4(acc[0], acc[1], acc[2], acc[3]);
            outp[1] = make_float4(acc[4], acc[5], acc[6], acc[7]);
            outp[2] = make_float4(acc[8], acc[9], acc[10], acc[11]);
            outp[3] = make_float4(acc[12], acc[13], acc[14], acc[15]);
#pragma unroll
            for (int k = 0; k < 16; k++) acc[k] = 0.0f;
        }
        grid_bar();

        // cooperative v-reduce: CTA owns 64 columns
        {
            int c0 = blk * 64;
            int col = tid & 63;
            int part = tid >> 6;       // 0..7, 16 chunks each
            float s = 0.0f;
#pragma unroll
            for (int k = 0; k < 16; k++) s += g_cpart[part * 16 + k][c0 + col];
            sred[part * 64 + col] = s;
            __syncthreads();
            if (tid < 64) {
                float t = 0.0f;
#pragma unroll
                for (int q = 0; q < 8; q++) t += sred[q * 64 + tid];
                g_v[c0 + tid] = INVN / t;
            }
        }
        grid_bar();
    }

    // -------- final pass: sum C .* plan, C = (lnALPHA - lnK)*reg*cmax --------
    float sigma = REG_E * __uint_as_float(g_cmax_bits);
    float vr[16];
    {
        const float4* vp = (const float4*)(g_v + tid * 16);
#pragma unroll
        for (int q = 0; q < 4; q++) {
            float4 vv = vp[q];
            vr[q * 4 + 0] = vv.x; vr[q * 4 + 1] = vv.y;
            vr[q * 4 + 2] = vv.z; vr[q * 4 + 3] = vv.w;
        }
    }
    float facc = 0.0f;
    for (int g = 0; g < NG; g++, G++) {
        const int b = G % NBUF;
        mwait(mbar_s[b], ph[b]); ph[b] ^= 1;
        const uint4* KU = bufs4[b];
        uint4 kreg[GR][2];
#pragma unroll
        for (int r = 0; r < GR; r++) {
            kreg[r][0] = KU[r * 1024 + tid * 2];
            kreg[r][1] = KU[r * 1024 + tid * 2 + 1];
        }
        __syncthreads();             // loads done -> buffer free
        issue_tile(G + NBUF, row_base, buf_s, mbar_s);   // no-op past end
#pragma unroll
        for (int r = 0; r < GR; r++) {
            float u = __ldg(&g_u[row_base + g * GR + r]);
            float rs = 0.0f;
#pragma unroll
            for (int j = 0; j < 2; j++) {
                float2 f0 = __half22float2(*(__half2*)&kreg[r][j].x);
                float2 f1 = __half22float2(*(__half2*)&kreg[r][j].y);
                float2 f2 = __half22float2(*(__half2*)&kreg[r][j].z);
                float2 f3 = __half22float2(*(__half2*)&kreg[r][j].w);
                rs += f0.x * vr[j * 8 + 0] * (LN_ALPHA - __logf(f0.x));
                rs += f0.y * vr[j * 8 + 1] * (LN_ALPHA - __logf(f0.y));
                rs += f1.x * vr[j * 8 + 2] * (LN_ALPHA - __logf(f1.x));
                rs += f1.y * vr[j * 8 + 3] * (LN_ALPHA - __logf(f1.y));
                rs += f2.x * vr[j * 8 + 4] * (LN_ALPHA - __logf(f2.x));
                rs += f2.y * vr[j * 8 + 5] * (LN_ALPHA - __logf(f2.y));
                rs += f3.x * vr[j * 8 + 6] * (LN_ALPHA - __logf(f3.x));
                rs += f3.y * vr[j * 8 + 7] * (LN_ALPHA - __logf(f3.y));
            }
            facc += u * rs;
        }
    }
    facc *= sigma;

    // block reduce -> g_partial[blk]
    {
        __syncthreads();
        sred[tid] = facc;
        __syncthreads();
        for (int s = 256; s > 0; s >>= 1) {
            if (tid < s) sred[tid] += sred[tid + s];
            __syncthreads();
        }
        if (tid == 0) g_partial[blk] = sred[0];
    }
    grid_bar();

    if (blk == 0) {
        float s = (tid < FB) ? g_partial[tid] : 0.0f;
        sred[tid] = s;
        __syncthreads();
        for (int st = 256; st > 0; st >>= 1) {
            if (tid < st) sred[tid] += sred[tid + st];
            __syncthreads();
        }
        if (tid == 0) out[0] = sred[0];
    }
}

// ---------------------------------------------------------------------------
extern "C" void kernel_launch(void* const* d_in, const int* in_sizes, int n_in,
                              void* d_out, int out_size) {
    const float* XP = (const float*)d_in[0];
    const float* XQ = (const float*)d_in[1];
    float* out = (float*)d_out;

    cudaFuncSetAttribute(sink_kernel,
                         cudaFuncAttributeMaxDynamicSharedMemorySize, FUSED_SMEM);

    init_kernel<<<NN / 256, 256>>>();
    norms_kernel<<<dim3(NN / 256, 2), 256>>>(XP, XQ);
    gemm_kernel<<<dim3(NN / 128, NN / 128), 256>>>(XP, XQ);
    exp_kernel<<<8192, 256>>>();
    sink_kernel<<<FB, 512, FUSED_SMEM>>>(out);
}